// round 2
// baseline (speedup 1.0000x reference)
#include <cuda_runtime.h>

#define BATCH 8
#define SEQ   1024
#define DIM   768
#define NHEAD 12
#define HDIM  64
#define BH    (BATCH * NHEAD)     // 96
#define MROWS (BATCH * SEQ)       // 8192
#define OUT_OFF ((size_t)MROWS * DIM)  // floats: out, then weights

// Scratch (alloc-free rule: __device__ globals).
__device__ float g_Q[BH * SEQ * HDIM];
__device__ float g_K[BH * SEQ * HDIM];
__device__ float g_V[BH * SEQ * HDIM];
__device__ float g_O[BH * SEQ * HDIM];

// ---------------------------------------------------------------------------
// Kernel 1: QKV projection. C = X @ W + b, output head-split [B,H,N,D].
// M=8192, N=768, K=768. 128x128 tile, 8x8 microtile, 256 threads.
// ---------------------------------------------------------------------------
__global__ __launch_bounds__(256) void proj_headsplit(
    const float* __restrict__ X, const float* __restrict__ W,
    const float* __restrict__ bias, int sel) {
    __shared__ float As[16][132];   // A transposed, +4 pad
    __shared__ float Bs[16][128];
    float* Out = (sel == 0) ? g_Q : (sel == 1) ? g_K : g_V;

    int tid = threadIdx.x;
    int tx = tid & 15, ty = tid >> 4;
    int row0 = blockIdx.y * 128;
    int col0 = blockIdx.x * 128;

    float acc[8][8] = {};
    for (int k0 = 0; k0 < DIM; k0 += 16) {
        #pragma unroll
        for (int p = 0; p < 2; ++p) {               // A: 128x16, transposed
            int i = tid + p * 256;                  // 0..511 float4 slots
            int r = i >> 2, c4 = i & 3;
            float4 v = *(const float4*)&X[(size_t)(row0 + r) * DIM + k0 + c4 * 4];
            As[c4 * 4 + 0][r] = v.x; As[c4 * 4 + 1][r] = v.y;
            As[c4 * 4 + 2][r] = v.z; As[c4 * 4 + 3][r] = v.w;
        }
        #pragma unroll
        for (int p = 0; p < 2; ++p) {               // B: 16x128
            int i = tid + p * 256;
            int r = i >> 5, c4 = i & 31;
            *(float4*)&Bs[r][c4 * 4] =
                *(const float4*)&W[(size_t)(k0 + r) * DIM + col0 + c4 * 4];
        }
        __syncthreads();
        #pragma unroll
        for (int kk = 0; kk < 16; ++kk) {
            float a[8], b[8];
            *(float4*)(a)     = *(float4*)&As[kk][ty * 8];
            *(float4*)(a + 4) = *(float4*)&As[kk][ty * 8 + 4];
            *(float4*)(b)     = *(float4*)&Bs[kk][tx * 8];
            *(float4*)(b + 4) = *(float4*)&Bs[kk][tx * 8 + 4];
            #pragma unroll
            for (int u = 0; u < 8; ++u)
                #pragma unroll
                for (int v = 0; v < 8; ++v) acc[u][v] += a[u] * b[v];
        }
        __syncthreads();
    }
    #pragma unroll
    for (int u = 0; u < 8; ++u) {
        int r = row0 + ty * 8 + u;                  // b*1024 + n
        int b = r >> 10, n = r & 1023;
        #pragma unroll
        for (int v = 0; v < 8; ++v) {
            int c = col0 + tx * 8 + v;              // h*64 + d
            int h = c >> 6, d = c & 63;
            Out[(((size_t)(b * NHEAD + h) * SEQ + n) * HDIM) + d] =
                acc[u][v] + bias[c];
        }
    }
}

// ---------------------------------------------------------------------------
// Kernel 2: scores = scale * Q @ K^T per (b,h). M=N=1024, K=64.
// 128x128 tile, 8x8 microtile. Writes into weights region of d_out.
// ---------------------------------------------------------------------------
__global__ __launch_bounds__(256) void scores_kernel(float* __restrict__ Wt) {
    __shared__ float As[16][132];   // Q transposed
    __shared__ float Bs[16][132];   // K transposed (gives K^T tile)
    int bh = blockIdx.z;
    int tid = threadIdx.x;
    int tx = tid & 15, ty = tid >> 4;
    int i0 = blockIdx.y * 128;
    int j0 = blockIdx.x * 128;
    const float* Qb = g_Q + (size_t)bh * SEQ * HDIM;
    const float* Kb = g_K + (size_t)bh * SEQ * HDIM;

    float acc[8][8] = {};
    for (int k0 = 0; k0 < HDIM; k0 += 16) {
        #pragma unroll
        for (int p = 0; p < 2; ++p) {
            int i = tid + p * 256;
            int r = i >> 2, c4 = i & 3;
            float4 va = *(const float4*)&Qb[(size_t)(i0 + r) * HDIM + k0 + c4 * 4];
            As[c4 * 4 + 0][r] = va.x; As[c4 * 4 + 1][r] = va.y;
            As[c4 * 4 + 2][r] = va.z; As[c4 * 4 + 3][r] = va.w;
            float4 vb = *(const float4*)&Kb[(size_t)(j0 + r) * HDIM + k0 + c4 * 4];
            Bs[c4 * 4 + 0][r] = vb.x; Bs[c4 * 4 + 1][r] = vb.y;
            Bs[c4 * 4 + 2][r] = vb.z; Bs[c4 * 4 + 3][r] = vb.w;
        }
        __syncthreads();
        #pragma unroll
        for (int kk = 0; kk < 16; ++kk) {
            float a[8], b[8];
            *(float4*)(a)     = *(float4*)&As[kk][ty * 8];
            *(float4*)(a + 4) = *(float4*)&As[kk][ty * 8 + 4];
            *(float4*)(b)     = *(float4*)&Bs[kk][tx * 8];
            *(float4*)(b + 4) = *(float4*)&Bs[kk][tx * 8 + 4];
            #pragma unroll
            for (int u = 0; u < 8; ++u)
                #pragma unroll
                for (int v = 0; v < 8; ++v) acc[u][v] += a[u] * b[v];
        }
        __syncthreads();
    }
    const float scale = 0.125f;
    #pragma unroll
    for (int u = 0; u < 8; ++u) {
        size_t rbase = ((size_t)bh * SEQ + i0 + ty * 8 + u) * SEQ + j0 + tx * 8;
        float4 o0 = make_float4(acc[u][0], acc[u][1], acc[u][2], acc[u][3]);
        float4 o1 = make_float4(acc[u][4], acc[u][5], acc[u][6], acc[u][7]);
        o0.x *= scale; o0.y *= scale; o0.z *= scale; o0.w *= scale;
        o1.x *= scale; o1.y *= scale; o1.z *= scale; o1.w *= scale;
        *(float4*)&Wt[rbase]     = o0;
        *(float4*)&Wt[rbase + 4] = o1;
    }
}

// ---------------------------------------------------------------------------
// Kernel 3: in-place row softmax. One block per row.
// ---------------------------------------------------------------------------
__global__ void softmax_kernel(float* __restrict__ Wt) {
    int row = blockIdx.x;
    float* p = Wt + (size_t)row * SEQ;
    int tid = threadIdx.x;                // 256 threads, 4 elems each
    float4 v = reinterpret_cast<float4*>(p)[tid];

    __shared__ float red[8];
    float m = fmaxf(fmaxf(v.x, v.y), fmaxf(v.z, v.w));
    #pragma unroll
    for (int o = 16; o; o >>= 1) m = fmaxf(m, __shfl_xor_sync(~0u, m, o));
    if ((tid & 31) == 0) red[tid >> 5] = m;
    __syncthreads();
    m = red[0];
    #pragma unroll
    for (int i = 1; i < 8; ++i) m = fmaxf(m, red[i]);
    __syncthreads();

    v.x = __expf(v.x - m); v.y = __expf(v.y - m);
    v.z = __expf(v.z - m); v.w = __expf(v.w - m);
    float s = v.x + v.y + v.z + v.w;
    #pragma unroll
    for (int o = 16; o; o >>= 1) s += __shfl_xor_sync(~0u, s, o);
    if ((tid & 31) == 0) red[tid >> 5] = s;
    __syncthreads();
    s = red[0];
    #pragma unroll
    for (int i = 1; i < 8; ++i) s += red[i];

    float inv = 1.0f / s;
    v.x *= inv; v.y *= inv; v.z *= inv; v.w *= inv;
    reinterpret_cast<float4*>(p)[tid] = v;
}

// ---------------------------------------------------------------------------
// Kernel 4: O = attn @ V per (b,h). M=1024, N=64, K=1024.
// 128x64 tile, 8x4 microtile, 256 threads.
// ---------------------------------------------------------------------------
__global__ __launch_bounds__(256) void av_kernel(const float* __restrict__ Wt) {
    __shared__ float As[16][132];   // attn transposed
    __shared__ float Bs[16][64];    // V natural
    int bh = blockIdx.z;
    int i0 = blockIdx.y * 128;
    int tid = threadIdx.x;
    int tx = tid & 15, ty = tid >> 4;
    const float* A  = Wt + (size_t)bh * SEQ * SEQ;
    const float* Vb = g_V + (size_t)bh * SEQ * HDIM;

    float acc[8][4] = {};
    for (int k0 = 0; k0 < SEQ; k0 += 16) {
        #pragma unroll
        for (int p = 0; p < 2; ++p) {               // A: 128x16 transposed
            int i = tid + p * 256;
            int r = i >> 2, c4 = i & 3;
            float4 v = *(const float4*)&A[(size_t)(i0 + r) * SEQ + k0 + c4 * 4];
            As[c4 * 4 + 0][r] = v.x; As[c4 * 4 + 1][r] = v.y;
            As[c4 * 4 + 2][r] = v.z; As[c4 * 4 + 3][r] = v.w;
        }
        {                                           // B: 16x64, 1 float4/thread
            int r = tid >> 4, c4 = tid & 15;
            *(float4*)&Bs[r][c4 * 4] =
                *(const float4*)&Vb[(size_t)(k0 + r) * HDIM + c4 * 4];
        }
        __syncthreads();
        #pragma unroll
        for (int kk = 0; kk < 16; ++kk) {
            float a[8], b[4];
            *(float4*)(a)     = *(float4*)&As[kk][ty * 8];
            *(float4*)(a + 4) = *(float4*)&As[kk][ty * 8 + 4];
            *(float4*)(b)     = *(float4*)&Bs[kk][tx * 4];
            #pragma unroll
            for (int u = 0; u < 8; ++u)
                #pragma unroll
                for (int v = 0; v < 4; ++v) acc[u][v] += a[u] * b[v];
        }
        __syncthreads();
    }
    #pragma unroll
    for (int u = 0; u < 8; ++u) {
        float4 o = make_float4(acc[u][0], acc[u][1], acc[u][2], acc[u][3]);
        *(float4*)&g_O[((size_t)bh * SEQ + i0 + ty * 8 + u) * HDIM + tx * 4] = o;
    }
}

// ---------------------------------------------------------------------------
// Kernel 5: out = merge_heads(O) @ Wo + bo. M=8192, N=768, K=768.
// ---------------------------------------------------------------------------
__global__ __launch_bounds__(256) void out_proj(
    const float* __restrict__ Wo, const float* __restrict__ bo,
    float* __restrict__ Out) {
    __shared__ float As[16][132];
    __shared__ float Bs[16][128];
    int tid = threadIdx.x;
    int tx = tid & 15, ty = tid >> 4;
    int row0 = blockIdx.y * 128;
    int col0 = blockIdx.x * 128;

    float acc[8][8] = {};
    for (int k0 = 0; k0 < DIM; k0 += 16) {
        #pragma unroll
        for (int p = 0; p < 2; ++p) {               // A gather from g_O
            int i = tid + p * 256;
            int r = i >> 2, c4 = i & 3;
            int gr = row0 + r;                      // b*1024 + n
            int b = gr >> 10, n = gr & 1023;
            int k = k0 + c4 * 4;                    // h*64+d, 4 contiguous in d
            int h = k >> 6, d = k & 63;
            float4 v = *(const float4*)
                &g_O[((size_t)(b * NHEAD + h) * SEQ + n) * HDIM + d];
            As[c4 * 4 + 0][r] = v.x; As[c4 * 4 + 1][r] = v.y;
            As[c4 * 4 + 2][r] = v.z; As[c4 * 4 + 3][r] = v.w;
        }
        #pragma unroll
        for (int p = 0; p < 2; ++p) {
            int i = tid + p * 256;
            int r = i >> 5, c4 = i & 31;
            *(float4*)&Bs[r][c4 * 4] =
                *(const float4*)&Wo[(size_t)(k0 + r) * DIM + col0 + c4 * 4];
        }
        __syncthreads();
        #pragma unroll
        for (int kk = 0; kk < 16; ++kk) {
            float a[8], b[8];
            *(float4*)(a)     = *(float4*)&As[kk][ty * 8];
            *(float4*)(a + 4) = *(float4*)&As[kk][ty * 8 + 4];
            *(float4*)(b)     = *(float4*)&Bs[kk][tx * 8];
            *(float4*)(b + 4) = *(float4*)&Bs[kk][tx * 8 + 4];
            #pragma unroll
            for (int u = 0; u < 8; ++u)
                #pragma unroll
                for (int v = 0; v < 8; ++v) acc[u][v] += a[u] * b[v];
        }
        __syncthreads();
    }
    #pragma unroll
    for (int u = 0; u < 8; ++u) {
        int r = row0 + ty * 8 + u;
        #pragma unroll
        for (int v = 0; v < 8; ++v) {
            int c = col0 + tx * 8 + v;
            Out[(size_t)r * DIM + c] = acc[u][v] + bo[c];
        }
    }
}

// ---------------------------------------------------------------------------
extern "C" void kernel_launch(void* const* d_in, const int* in_sizes, int n_in,
                              void* d_out, int out_size) {
    const float* x  = (const float*)d_in[0];
    const float* Wq = (const float*)d_in[1];
    const float* bq = (const float*)d_in[2];
    const float* Wk = (const float*)d_in[3];
    const float* bk = (const float*)d_in[4];
    const float* Wv = (const float*)d_in[5];
    const float* bv = (const float*)d_in[6];
    const float* Wo = (const float*)d_in[7];
    const float* bo = (const float*)d_in[8];

    float* out = (float*)d_out;             // [8,1024,768]
    float* wts = out + OUT_OFF;             // [8,12,1024,1024]

    dim3 gProj(DIM / 128, MROWS / 128);     // (6, 64)
    proj_headsplit<<<gProj, 256>>>(x, Wq, bq, 0);
    proj_headsplit<<<gProj, 256>>>(x, Wk, bk, 1);
    proj_headsplit<<<gProj, 256>>>(x, Wv, bv, 2);

    scores_kernel<<<dim3(SEQ / 128, SEQ / 128, BH), 256>>>(wts);  // (8,8,96)
    softmax_kernel<<<BH * SEQ, 256>>>(wts);
    av_kernel<<<dim3(1, SEQ / 128, BH), 256>>>(wts);              // (1,8,96)
    out_proj<<<gProj, 256>>>(Wo, bo, out);
}

// round 4
// speedup vs baseline: 1.8834x; 1.8834x over previous
#include <cuda_runtime.h>
#include <cuda_bf16.h>
#include <cstdint>

#define BATCH 8
#define SEQ   1024
#define DIM   768
#define NHEAD 12
#define HDIM  64
#define BH    (BATCH * NHEAD)     // 96
#define MROWS (BATCH * SEQ)       // 8192
#define OUT_OFF ((size_t)MROWS * DIM)

// ---------------- scratch (__device__ globals; no allocs allowed) ----------
__device__ float g_Q[MROWS * DIM];
__device__ float g_K[MROWS * DIM];
__device__ float g_V[MROWS * DIM];
__device__ float g_O[MROWS * DIM];
__device__ __nv_bfloat16 g_Xh[MROWS * DIM];
__device__ __nv_bfloat16 g_Xl[MROWS * DIM];
__device__ __nv_bfloat16 g_Oh[MROWS * DIM];
__device__ __nv_bfloat16 g_Ol[MROWS * DIM];
__device__ __nv_bfloat16 g_WTh[4 * DIM * DIM];   // W^T, hi  ([n][k])
__device__ __nv_bfloat16 g_WTl[4 * DIM * DIM];   // W^T, lo

// ---------------- helpers --------------------------------------------------
__device__ __forceinline__ uint32_t smem_u32(const void* p) {
    uint32_t a;
    asm("{ .reg .u64 t; cvta.to.shared.u64 t, %1; cvt.u32.u64 %0, t; }"
        : "=r"(a) : "l"(p));
    return a;
}
#define CP_ASYNC16(sm, gp) \
    asm volatile("cp.async.cg.shared.global [%0], [%1], 16;" \
                 :: "r"(sm), "l"(gp) : "memory")
#define CP_COMMIT() asm volatile("cp.async.commit_group;" ::: "memory")
#define CP_WAIT1()  asm volatile("cp.async.wait_group 1;" ::: "memory")
#define CP_WAIT0()  asm volatile("cp.async.wait_group 0;" ::: "memory")
#define LDSM_X4(r0, r1, r2, r3, addr) \
    asm volatile("ldmatrix.sync.aligned.m8n8.x4.shared.b16 {%0,%1,%2,%3}, [%4];" \
                 : "=r"(r0), "=r"(r1), "=r"(r2), "=r"(r3) : "r"(addr))
#define MMA16816(d, a, b) \
    asm volatile("mma.sync.aligned.m16n8k16.row.col.f32.bf16.bf16.f32 " \
                 "{%0,%1,%2,%3}, {%4,%5,%6,%7}, {%8,%9}, {%0,%1,%2,%3};" \
                 : "+f"((d)[0]), "+f"((d)[1]), "+f"((d)[2]), "+f"((d)[3]) \
                 : "r"((a)[0]), "r"((a)[1]), "r"((a)[2]), "r"((a)[3]), \
                   "r"((b)[0]), "r"((b)[1]))

// ---------------------------------------------------------------------------
// fp32 -> bf16 hi/lo split (flat)
// ---------------------------------------------------------------------------
__global__ void split_kernel(const float* __restrict__ src,
                             __nv_bfloat16* __restrict__ hi,
                             __nv_bfloat16* __restrict__ lo, int n4) {
    int i = blockIdx.x * blockDim.x + threadIdx.x;
    if (i >= n4) return;
    float4 v = reinterpret_cast<const float4*>(src)[i];
    __nv_bfloat16 h0 = __float2bfloat16(v.x);
    __nv_bfloat16 h1 = __float2bfloat16(v.y);
    __nv_bfloat16 h2 = __float2bfloat16(v.z);
    __nv_bfloat16 h3 = __float2bfloat16(v.w);
    __nv_bfloat16 l0 = __float2bfloat16(v.x - __bfloat162float(h0));
    __nv_bfloat16 l1 = __float2bfloat16(v.y - __bfloat162float(h1));
    __nv_bfloat16 l2 = __float2bfloat16(v.z - __bfloat162float(h2));
    __nv_bfloat16 l3 = __float2bfloat16(v.w - __bfloat162float(h3));
    __nv_bfloat162 a, b, c, d;
    a.x = h0; a.y = h1; b.x = h2; b.y = h3;
    c.x = l0; c.y = l1; d.x = l2; d.y = l3;
    reinterpret_cast<__nv_bfloat162*>(hi)[2 * i]     = a;
    reinterpret_cast<__nv_bfloat162*>(hi)[2 * i + 1] = b;
    reinterpret_cast<__nv_bfloat162*>(lo)[2 * i]     = c;
    reinterpret_cast<__nv_bfloat162*>(lo)[2 * i + 1] = d;
}

// fp32 W[k][n] -> bf16 hi/lo W^T[n][k]
__global__ void splitT_kernel(const float* __restrict__ W,
                              __nv_bfloat16* __restrict__ hiT,
                              __nv_bfloat16* __restrict__ loT) {
    int i = blockIdx.x * blockDim.x + threadIdx.x;
    if (i >= DIM * DIM) return;
    int k = i / DIM, n = i - k * DIM;
    float a = W[i];
    __nv_bfloat16 h = __float2bfloat16(a);
    hiT[n * DIM + k] = h;
    loT[n * DIM + k] = __float2bfloat16(a - __bfloat162float(h));
}

// ---------------------------------------------------------------------------
// mma.sync bf16x3 GEMM: C[8192x768] = A @ B^T + bias  (B = W^T, [n][k]).
// 128x128x32 block tile, 8 warps (2x4), warp tile 64x32, 2-stage cp.async.
// Smem tile: 128 rows x 32 bf16, padded row stride 40 halves (80 B).
// ---------------------------------------------------------------------------
#define TILE_B   10240                 // 128*40*2 bytes
#define STAGE_B  (4 * TILE_B)          // Ah, Al, Bh, Bl
#define GSMEM    (2 * STAGE_B)         // 81920

__global__ __launch_bounds__(256, 1)
void gemm_mma_bf16x3(const __nv_bfloat16* __restrict__ Ah,
                     const __nv_bfloat16* __restrict__ Al,
                     const __nv_bfloat16* __restrict__ Bh,
                     const __nv_bfloat16* __restrict__ Bl,
                     const float* __restrict__ bias, float* __restrict__ C) {
    extern __shared__ char sm[];
    const int tid = threadIdx.x;
    const int lane = tid & 31;
    const int warp = tid >> 5;
    const int wm = warp >> 2, wn = warp & 3;     // 2 x 4 warp grid
    const size_t row0 = (size_t)blockIdx.y * 128;
    const size_t col0 = (size_t)blockIdx.x * 128;
    const uint32_t smb = smem_u32(sm);

    float acc[4][4][4];
    #pragma unroll
    for (int i = 0; i < 4; ++i)
        #pragma unroll
        for (int j = 0; j < 4; ++j)
            #pragma unroll
            for (int q = 0; q < 4; ++q) acc[i][j][q] = 0.f;

    // chunk mapping for cp.async: 512 16B-chunks per tile, 2 per thread
    const int r_c0 = tid >> 2, j_c0 = tid & 3;           // chunk tid
    const int r_c1 = (tid + 256) >> 2, j_c1 = (tid + 256) & 3;

    // ---- issue slab s into stage st ----
    auto issue = [&](int s, int st) {
        const int k0 = s * 32;
        const uint32_t sb = smb + st * STAGE_B;
        const __nv_bfloat16* gAh = Ah + (row0 + r_c0) * DIM + k0 + j_c0 * 8;
        const __nv_bfloat16* gAl = Al + (row0 + r_c0) * DIM + k0 + j_c0 * 8;
        const __nv_bfloat16* gBh = Bh + (col0 + r_c0) * DIM + k0 + j_c0 * 8;
        const __nv_bfloat16* gBl = Bl + (col0 + r_c0) * DIM + k0 + j_c0 * 8;
        uint32_t d0 = sb + r_c0 * 80 + j_c0 * 16;
        CP_ASYNC16(d0,            gAh);
        CP_ASYNC16(d0 + TILE_B,   gAl);
        CP_ASYNC16(d0 + 2*TILE_B, gBh);
        CP_ASYNC16(d0 + 3*TILE_B, gBl);
        const __nv_bfloat16* gAh1 = Ah + (row0 + r_c1) * DIM + k0 + j_c1 * 8;
        const __nv_bfloat16* gAl1 = Al + (row0 + r_c1) * DIM + k0 + j_c1 * 8;
        const __nv_bfloat16* gBh1 = Bh + (col0 + r_c1) * DIM + k0 + j_c1 * 8;
        const __nv_bfloat16* gBl1 = Bl + (col0 + r_c1) * DIM + k0 + j_c1 * 8;
        uint32_t d1 = sb + r_c1 * 80 + j_c1 * 16;
        CP_ASYNC16(d1,            gAh1);
        CP_ASYNC16(d1 + TILE_B,   gAl1);
        CP_ASYNC16(d1 + 2*TILE_B, gBh1);
        CP_ASYNC16(d1 + 3*TILE_B, gBl1);
        CP_COMMIT();
    };

    // fragment smem address precompute (lane-dependent parts)
    const int a_row_l = (lane & 15);            // + mi*16 + wm*64
    const int a_col_l = (lane >> 4) << 3;       // + ks*16
    const int b_row_l = (lane & 7) + ((lane >> 4) << 3);  // + nj*16 + wn*32
    const int b_col_l = ((lane >> 3) & 1) << 3; // + ks*16

    issue(0, 0);
    for (int s = 0; s < 24; ++s) {
        if (s + 1 < 24) { issue(s + 1, (s + 1) & 1); CP_WAIT1(); }
        else           { CP_WAIT0(); }
        __syncthreads();

        const uint32_t sb = smb + (s & 1) * STAGE_B;
        const uint32_t tAh = sb, tAl = sb + TILE_B;
        const uint32_t tBh = sb + 2 * TILE_B, tBl = sb + 3 * TILE_B;

        #pragma unroll
        for (int ks = 0; ks < 2; ++ks) {
            uint32_t ah[4][4], al[4][4], bh[4][2], bl[4][2];
            #pragma unroll
            for (int mi = 0; mi < 4; ++mi) {
                uint32_t off = (uint32_t)((wm * 64 + mi * 16 + a_row_l) * 80 +
                                          (ks * 16 + a_col_l) * 2);
                LDSM_X4(ah[mi][0], ah[mi][1], ah[mi][2], ah[mi][3], tAh + off);
                LDSM_X4(al[mi][0], al[mi][1], al[mi][2], al[mi][3], tAl + off);
            }
            #pragma unroll
            for (int nj = 0; nj < 2; ++nj) {
                uint32_t off = (uint32_t)((wn * 32 + nj * 16 + b_row_l) * 80 +
                                          (ks * 16 + b_col_l) * 2);
                uint32_t t0, t1, t2, t3;
                LDSM_X4(t0, t1, t2, t3, tBh + off);
                bh[nj * 2][0] = t0; bh[nj * 2][1] = t1;
                bh[nj * 2 + 1][0] = t2; bh[nj * 2 + 1][1] = t3;
                LDSM_X4(t0, t1, t2, t3, tBl + off);
                bl[nj * 2][0] = t0; bl[nj * 2][1] = t1;
                bl[nj * 2 + 1][0] = t2; bl[nj * 2 + 1][1] = t3;
            }
            #pragma unroll
            for (int mi = 0; mi < 4; ++mi)
                #pragma unroll
                for (int ni = 0; ni < 4; ++ni) {
                    MMA16816(acc[mi][ni], ah[mi], bh[ni]);
                    MMA16816(acc[mi][ni], al[mi], bh[ni]);
                    MMA16816(acc[mi][ni], ah[mi], bl[ni]);
                }
        }
        __syncthreads();
    }

    // epilogue: c layout — thread holds rows (t/4, t/4+8), cols (t%4)*2, +1
    const int mbase = (int)row0 + wm * 64;
    const int nbase = (int)col0 + wn * 32;
    #pragma unroll
    for (int mi = 0; mi < 4; ++mi) {
        #pragma unroll
        for (int ni = 0; ni < 4; ++ni) {
            int r = mbase + mi * 16 + (lane >> 2);
            int c = nbase + ni * 8 + (lane & 3) * 2;
            float b0 = bias[c], b1 = bias[c + 1];
            float2 o0 = make_float2(acc[mi][ni][0] + b0, acc[mi][ni][1] + b1);
            float2 o1 = make_float2(acc[mi][ni][2] + b0, acc[mi][ni][3] + b1);
            *(float2*)&C[(size_t)r * DIM + c] = o0;
            *(float2*)&C[(size_t)(r + 8) * DIM + c] = o1;
        }
    }
}

// ---------------------------------------------------------------------------
// scores = scale * Q @ K^T per (b,h). 64x64 tiles, flat [8192][768] layout.
// ---------------------------------------------------------------------------
__global__ void scores_kernel(float* __restrict__ Wt) {
    __shared__ float Qs[64][65];
    __shared__ float Ks[64][65];
    int bh = blockIdx.z;
    int b = bh / NHEAD, h = bh - b * NHEAD;
    int tid = threadIdx.x;
    int tx = tid & 15, ty = tid >> 4;
    int i0 = blockIdx.y * 64;
    int j0 = blockIdx.x * 64;
    const float* Qb = g_Q + (size_t)b * SEQ * DIM + h * HDIM;
    const float* Kb = g_K + (size_t)b * SEQ * DIM + h * HDIM;

    #pragma unroll
    for (int i = tid; i < 64 * 64; i += 256) {
        int r = i >> 6, c = i & 63;
        Qs[r][c] = Qb[(size_t)(i0 + r) * DIM + c];
        Ks[r][c] = Kb[(size_t)(j0 + r) * DIM + c];
    }
    __syncthreads();

    float acc[4][4] = {};
    #pragma unroll 16
    for (int kk = 0; kk < 64; ++kk) {
        float a[4], bb[4];
        #pragma unroll
        for (int u = 0; u < 4; ++u) a[u] = Qs[ty * 4 + u][kk];
        #pragma unroll
        for (int v = 0; v < 4; ++v) bb[v] = Ks[tx * 4 + v][kk];
        #pragma unroll
        for (int u = 0; u < 4; ++u)
            #pragma unroll
            for (int v = 0; v < 4; ++v) acc[u][v] += a[u] * bb[v];
    }
    const float scale = 0.125f;
    #pragma unroll
    for (int u = 0; u < 4; ++u) {
        size_t rbase = ((size_t)bh * SEQ + i0 + ty * 4 + u) * SEQ;
        #pragma unroll
        for (int v = 0; v < 4; ++v)
            Wt[rbase + j0 + tx * 4 + v] = acc[u][v] * scale;
    }
}

// ---------------------------------------------------------------------------
__global__ void softmax_kernel(float* __restrict__ Wt) {
    int row = blockIdx.x;
    float* p = Wt + (size_t)row * SEQ;
    int tid = threadIdx.x;
    float4 v = reinterpret_cast<float4*>(p)[tid];

    __shared__ float red[8];
    float m = fmaxf(fmaxf(v.x, v.y), fmaxf(v.z, v.w));
    #pragma unroll
    for (int o = 16; o; o >>= 1) m = fmaxf(m, __shfl_xor_sync(~0u, m, o));
    if ((tid & 31) == 0) red[tid >> 5] = m;
    __syncthreads();
    m = red[0];
    #pragma unroll
    for (int i = 1; i < 8; ++i) m = fmaxf(m, red[i]);
    __syncthreads();

    v.x = __expf(v.x - m); v.y = __expf(v.y - m);
    v.z = __expf(v.z - m); v.w = __expf(v.w - m);
    float s = v.x + v.y + v.z + v.w;
    #pragma unroll
    for (int o = 16; o; o >>= 1) s += __shfl_xor_sync(~0u, s, o);
    if ((tid & 31) == 0) red[tid >> 5] = s;
    __syncthreads();
    s = red[0];
    #pragma unroll
    for (int i = 1; i < 8; ++i) s += red[i];

    float inv = 1.0f / s;
    v.x *= inv; v.y *= inv; v.z *= inv; v.w *= inv;
    reinterpret_cast<float4*>(p)[tid] = v;
}

// ---------------------------------------------------------------------------
// O = attn @ V per (b,h). Writes flat g_O [8192][768].
// ---------------------------------------------------------------------------
__global__ void av_kernel(const float* __restrict__ Wt) {
    __shared__ float As[64][17];
    __shared__ float Bs[16][64];
    int bh = blockIdx.z;
    int b = bh / NHEAD, h = bh - b * NHEAD;
    int i0 = blockIdx.y * 64;
    int tid = threadIdx.x;
    int tx = tid & 15, ty = tid >> 4;
    const float* A = Wt + (size_t)bh * SEQ * SEQ;
    const float* Vb = g_V + (size_t)b * SEQ * DIM + h * HDIM;

    float acc[4][4] = {};
    for (int k0 = 0; k0 < SEQ; k0 += 16) {
        #pragma unroll
        for (int i = tid; i < 64 * 16; i += 256) {
            int r = i >> 4, c = i & 15;
            As[r][c] = A[(size_t)(i0 + r) * SEQ + k0 + c];
        }
        #pragma unroll
        for (int i = tid; i < 16 * 64; i += 256) {
            int r = i >> 6, c = i & 63;
            Bs[r][c] = Vb[(size_t)(k0 + r) * DIM + c];
        }
        __syncthreads();
        #pragma unroll
        for (int kk = 0; kk < 16; ++kk) {
            float a[4], bb[4];
            #pragma unroll
            for (int u = 0; u < 4; ++u) a[u] = As[ty * 4 + u][kk];
            #pragma unroll
            for (int v = 0; v < 4; ++v) bb[v] = Bs[kk][tx * 4 + v];
            #pragma unroll
            for (int u = 0; u < 4; ++u)
                #pragma unroll
                for (int v = 0; v < 4; ++v) acc[u][v] += a[u] * bb[v];
        }
        __syncthreads();
    }
    #pragma unroll
    for (int u = 0; u < 4; ++u)
        #pragma unroll
        for (int v = 0; v < 4; ++v)
            g_O[((size_t)b * SEQ + i0 + ty * 4 + u) * DIM + h * HDIM + tx * 4 + v] =
                acc[u][v];
}

// ---------------------------------------------------------------------------
extern "C" void kernel_launch(void* const* d_in, const int* in_sizes, int n_in,
                              void* d_out, int out_size) {
    const float* x  = (const float*)d_in[0];
    const float* Wq = (const float*)d_in[1];
    const float* bq = (const float*)d_in[2];
    const float* Wk = (const float*)d_in[3];
    const float* bk = (const float*)d_in[4];
    const float* Wv = (const float*)d_in[5];
    const float* bv = (const float*)d_in[6];
    const float* Wo = (const float*)d_in[7];
    const float* bo = (const float*)d_in[8];

    float* out = (float*)d_out;
    float* wts = out + OUT_OFF;

    cudaFuncSetAttribute(gemm_mma_bf16x3,
                         cudaFuncAttributeMaxDynamicSharedMemorySize, GSMEM);

    __nv_bfloat16 *Xh, *Xl, *Oh, *Ol, *WTh, *WTl;
    cudaGetSymbolAddress((void**)&Xh, g_Xh);
    cudaGetSymbolAddress((void**)&Xl, g_Xl);
    cudaGetSymbolAddress((void**)&Oh, g_Oh);
    cudaGetSymbolAddress((void**)&Ol, g_Ol);
    cudaGetSymbolAddress((void**)&WTh, g_WTh);
    cudaGetSymbolAddress((void**)&WTl, g_WTl);
    float *Qf, *Kf, *Vf, *Of;
    cudaGetSymbolAddress((void**)&Qf, g_Q);
    cudaGetSymbolAddress((void**)&Kf, g_K);
    cudaGetSymbolAddress((void**)&Vf, g_V);
    cudaGetSymbolAddress((void**)&Of, g_O);

    const int NELEM = MROWS * DIM;
    split_kernel<<<NELEM / 4 / 256, 256>>>(x, Xh, Xl, NELEM / 4);
    const int WT_BLK = (DIM * DIM + 255) / 256;
    splitT_kernel<<<WT_BLK, 256>>>(Wq, WTh + 0 * DIM * DIM, WTl + 0 * DIM * DIM);
    splitT_kernel<<<WT_BLK, 256>>>(Wk, WTh + 1 * DIM * DIM, WTl + 1 * DIM * DIM);
    splitT_kernel<<<WT_BLK, 256>>>(Wv, WTh + 2 * DIM * DIM, WTl + 2 * DIM * DIM);
    splitT_kernel<<<WT_BLK, 256>>>(Wo, WTh + 3 * DIM * DIM, WTl + 3 * DIM * DIM);

    dim3 gG(DIM / 128, MROWS / 128);            // (6, 64)
    gemm_mma_bf16x3<<<gG, 256, GSMEM>>>(Xh, Xl, WTh + 0 * DIM * DIM,
                                        WTl + 0 * DIM * DIM, bq, Qf);
    gemm_mma_bf16x3<<<gG, 256, GSMEM>>>(Xh, Xl, WTh + 1 * DIM * DIM,
                                        WTl + 1 * DIM * DIM, bk, Kf);
    gemm_mma_bf16x3<<<gG, 256, GSMEM>>>(Xh, Xl, WTh + 2 * DIM * DIM,
                                        WTl + 2 * DIM * DIM, bv, Vf);

    scores_kernel<<<dim3(SEQ / 64, SEQ / 64, BH), 256>>>(wts);
    softmax_kernel<<<BH * SEQ, 256>>>(wts);
    av_kernel<<<dim3(1, SEQ / 64, BH), 256>>>(wts);

    split_kernel<<<NELEM / 4 / 256, 256>>>(Of, Oh, Ol, NELEM / 4);
    gemm_mma_bf16x3<<<gG, 256, GSMEM>>>(Oh, Ol, WTh + 3 * DIM * DIM,
                                        WTl + 3 * DIM * DIM, bo, out);
}

// round 5
// speedup vs baseline: 3.2992x; 1.7517x over previous
#include <cuda_runtime.h>
#include <cuda_bf16.h>
#include <cstdint>

#define BATCH 8
#define SEQ   1024
#define DIM   768
#define NHEAD 12
#define HDIM  64
#define BH    (BATCH * NHEAD)     // 96
#define MROWS (BATCH * SEQ)       // 8192
#define OUT_OFF ((size_t)MROWS * DIM)

// ---------------- scratch (__device__ globals; no allocs allowed) ----------
__device__ __nv_bfloat16 g_Xh[MROWS * DIM];
__device__ __nv_bfloat16 g_Xl[MROWS * DIM];
__device__ __nv_bfloat16 g_Qh[MROWS * DIM];
__device__ __nv_bfloat16 g_Ql[MROWS * DIM];
__device__ __nv_bfloat16 g_Kh[MROWS * DIM];
__device__ __nv_bfloat16 g_Kl[MROWS * DIM];
__device__ __nv_bfloat16 g_VTh[BH * HDIM * SEQ];  // [bh*64+d][n]
__device__ __nv_bfloat16 g_VTl[BH * HDIM * SEQ];
__device__ __nv_bfloat16 g_Oh[MROWS * DIM];
__device__ __nv_bfloat16 g_Ol[MROWS * DIM];
__device__ __nv_bfloat16 g_WTh[4 * DIM * DIM];    // W^T hi ([n][k])
__device__ __nv_bfloat16 g_WTl[4 * DIM * DIM];
__device__ __nv_bfloat16 g_Ph[(size_t)BH * SEQ * SEQ];
__device__ __nv_bfloat16 g_Pl[(size_t)BH * SEQ * SEQ];

// ---------------- helpers --------------------------------------------------
__device__ __forceinline__ uint32_t smem_u32(const void* p) {
    uint32_t a;
    asm("{ .reg .u64 t; cvta.to.shared.u64 t, %1; cvt.u32.u64 %0, t; }"
        : "=r"(a) : "l"(p));
    return a;
}
#define CP_ASYNC16(sm, gp) \
    asm volatile("cp.async.cg.shared.global [%0], [%1], 16;" \
                 :: "r"(sm), "l"(gp) : "memory")
#define CP_COMMIT() asm volatile("cp.async.commit_group;" ::: "memory")
#define CP_WAIT1()  asm volatile("cp.async.wait_group 1;" ::: "memory")
#define CP_WAIT0()  asm volatile("cp.async.wait_group 0;" ::: "memory")
#define LDSM_X4(r0, r1, r2, r3, addr) \
    asm volatile("ldmatrix.sync.aligned.m8n8.x4.shared.b16 {%0,%1,%2,%3}, [%4];" \
                 : "=r"(r0), "=r"(r1), "=r"(r2), "=r"(r3) : "r"(addr))
#define MMA16816(d, a, b) \
    asm volatile("mma.sync.aligned.m16n8k16.row.col.f32.bf16.bf16.f32 " \
                 "{%0,%1,%2,%3}, {%4,%5,%6,%7}, {%8,%9}, {%0,%1,%2,%3};" \
                 : "+f"((d)[0]), "+f"((d)[1]), "+f"((d)[2]), "+f"((d)[3]) \
                 : "r"((a)[0]), "r"((a)[1]), "r"((a)[2]), "r"((a)[3]), \
                   "r"((b)[0]), "r"((b)[1]))

__device__ __forceinline__ __nv_bfloat162 split_hi2(float a, float b,
                                                    __nv_bfloat162& lo) {
    __nv_bfloat16 h0 = __float2bfloat16(a);
    __nv_bfloat16 h1 = __float2bfloat16(b);
    lo.x = __float2bfloat16(a - __bfloat162float(h0));
    lo.y = __float2bfloat16(b - __bfloat162float(h1));
    __nv_bfloat162 hi; hi.x = h0; hi.y = h1;
    return hi;
}

// ---------------------------------------------------------------------------
__global__ void split_kernel(const float* __restrict__ src,
                             __nv_bfloat16* __restrict__ hi,
                             __nv_bfloat16* __restrict__ lo, int n4) {
    int i = blockIdx.x * blockDim.x + threadIdx.x;
    if (i >= n4) return;
    float4 v = reinterpret_cast<const float4*>(src)[i];
    __nv_bfloat162 l0, l1;
    __nv_bfloat162 h0 = split_hi2(v.x, v.y, l0);
    __nv_bfloat162 h1 = split_hi2(v.z, v.w, l1);
    reinterpret_cast<__nv_bfloat162*>(hi)[2 * i]     = h0;
    reinterpret_cast<__nv_bfloat162*>(hi)[2 * i + 1] = h1;
    reinterpret_cast<__nv_bfloat162*>(lo)[2 * i]     = l0;
    reinterpret_cast<__nv_bfloat162*>(lo)[2 * i + 1] = l1;
}

__global__ void splitT_kernel(const float* __restrict__ W,
                              __nv_bfloat16* __restrict__ hiT,
                              __nv_bfloat16* __restrict__ loT) {
    int i = blockIdx.x * blockDim.x + threadIdx.x;
    if (i >= DIM * DIM) return;
    int k = i / DIM, n = i - k * DIM;
    float a = W[i];
    __nv_bfloat16 h = __float2bfloat16(a);
    hiT[n * DIM + k] = h;
    loT[n * DIM + k] = __float2bfloat16(a - __bfloat162float(h));
}

// ---------------------------------------------------------------------------
// mma.sync bf16x3 GEMM: 128x128x32 tiles, 8 warps (2x4), warp 64x32.
// mode 0: fp32 C + bias.  mode 1: bf16 hi/lo flat + bias.
// mode 2: bf16 hi/lo transposed VT[bh*64+d][n] + bias.
// ---------------------------------------------------------------------------
#define TILE_B   10240
#define STAGE_B  (4 * TILE_B)
#define GSMEM    (2 * STAGE_B)         // 81920

__global__ __launch_bounds__(256, 1)
void gemm_mma_bf16x3(const __nv_bfloat16* __restrict__ Ah,
                     const __nv_bfloat16* __restrict__ Al,
                     const __nv_bfloat16* __restrict__ Bh,
                     const __nv_bfloat16* __restrict__ Bl,
                     const float* __restrict__ bias,
                     float* __restrict__ Cf,
                     __nv_bfloat16* __restrict__ Ch,
                     __nv_bfloat16* __restrict__ Cl, int mode) {
    extern __shared__ char sm[];
    const int tid = threadIdx.x;
    const int lane = tid & 31;
    const int warp = tid >> 5;
    const int wm = warp >> 2, wn = warp & 3;
    const size_t row0 = (size_t)blockIdx.y * 128;
    const size_t col0 = (size_t)blockIdx.x * 128;
    const uint32_t smb = smem_u32(sm);

    float acc[4][4][4];
    #pragma unroll
    for (int i = 0; i < 4; ++i)
        #pragma unroll
        for (int j = 0; j < 4; ++j)
            #pragma unroll
            for (int q = 0; q < 4; ++q) acc[i][j][q] = 0.f;

    const int r_c0 = tid >> 2, j_c0 = tid & 3;
    const int r_c1 = (tid + 256) >> 2, j_c1 = (tid + 256) & 3;

    auto issue = [&](int s, int st) {
        const int k0 = s * 32;
        const uint32_t sb = smb + st * STAGE_B;
        uint32_t d0 = sb + r_c0 * 80 + j_c0 * 16;
        CP_ASYNC16(d0,            Ah + (row0 + r_c0) * DIM + k0 + j_c0 * 8);
        CP_ASYNC16(d0 + TILE_B,   Al + (row0 + r_c0) * DIM + k0 + j_c0 * 8);
        CP_ASYNC16(d0 + 2*TILE_B, Bh + (col0 + r_c0) * DIM + k0 + j_c0 * 8);
        CP_ASYNC16(d0 + 3*TILE_B, Bl + (col0 + r_c0) * DIM + k0 + j_c0 * 8);
        uint32_t d1 = sb + r_c1 * 80 + j_c1 * 16;
        CP_ASYNC16(d1,            Ah + (row0 + r_c1) * DIM + k0 + j_c1 * 8);
        CP_ASYNC16(d1 + TILE_B,   Al + (row0 + r_c1) * DIM + k0 + j_c1 * 8);
        CP_ASYNC16(d1 + 2*TILE_B, Bh + (col0 + r_c1) * DIM + k0 + j_c1 * 8);
        CP_ASYNC16(d1 + 3*TILE_B, Bl + (col0 + r_c1) * DIM + k0 + j_c1 * 8);
        CP_COMMIT();
    };

    const int a_row_l = (lane & 15);
    const int a_col_l = (lane >> 4) << 3;
    const int b_row_l = (lane & 7) + ((lane >> 4) << 3);
    const int b_col_l = ((lane >> 3) & 1) << 3;

    issue(0, 0);
    for (int s = 0; s < 24; ++s) {
        if (s + 1 < 24) { issue(s + 1, (s + 1) & 1); CP_WAIT1(); }
        else           { CP_WAIT0(); }
        __syncthreads();
        const uint32_t sb = smb + (s & 1) * STAGE_B;
        const uint32_t tAh = sb, tAl = sb + TILE_B;
        const uint32_t tBh = sb + 2 * TILE_B, tBl = sb + 3 * TILE_B;
        #pragma unroll
        for (int ks = 0; ks < 2; ++ks) {
            uint32_t ah[4][4], al[4][4], bh[4][2], bl[4][2];
            #pragma unroll
            for (int mi = 0; mi < 4; ++mi) {
                uint32_t off = (uint32_t)((wm * 64 + mi * 16 + a_row_l) * 80 +
                                          (ks * 16 + a_col_l) * 2);
                LDSM_X4(ah[mi][0], ah[mi][1], ah[mi][2], ah[mi][3], tAh + off);
                LDSM_X4(al[mi][0], al[mi][1], al[mi][2], al[mi][3], tAl + off);
            }
            #pragma unroll
            for (int nj = 0; nj < 2; ++nj) {
                uint32_t off = (uint32_t)((wn * 32 + nj * 16 + b_row_l) * 80 +
                                          (ks * 16 + b_col_l) * 2);
                uint32_t t0, t1, t2, t3;
                LDSM_X4(t0, t1, t2, t3, tBh + off);
                bh[nj * 2][0] = t0; bh[nj * 2][1] = t1;
                bh[nj * 2 + 1][0] = t2; bh[nj * 2 + 1][1] = t3;
                LDSM_X4(t0, t1, t2, t3, tBl + off);
                bl[nj * 2][0] = t0; bl[nj * 2][1] = t1;
                bl[nj * 2 + 1][0] = t2; bl[nj * 2 + 1][1] = t3;
            }
            #pragma unroll
            for (int mi = 0; mi < 4; ++mi)
                #pragma unroll
                for (int ni = 0; ni < 4; ++ni) {
                    MMA16816(acc[mi][ni], ah[mi], bh[ni]);
                    MMA16816(acc[mi][ni], al[mi], bh[ni]);
                    MMA16816(acc[mi][ni], ah[mi], bl[ni]);
                }
        }
        __syncthreads();
    }

    const int mbase = (int)row0 + wm * 64;
    const int nbase = (int)col0 + wn * 32;
    #pragma unroll
    for (int mi = 0; mi < 4; ++mi) {
        #pragma unroll
        for (int ni = 0; ni < 4; ++ni) {
            int r = mbase + mi * 16 + (lane >> 2);
            int c = nbase + ni * 8 + (lane & 3) * 2;
            float b0 = bias[c], b1 = bias[c + 1];
            float v00 = acc[mi][ni][0] + b0, v01 = acc[mi][ni][1] + b1;
            float v10 = acc[mi][ni][2] + b0, v11 = acc[mi][ni][3] + b1;
            if (mode == 0) {
                *(float2*)&Cf[(size_t)r * DIM + c] = make_float2(v00, v01);
                *(float2*)&Cf[(size_t)(r + 8) * DIM + c] = make_float2(v10, v11);
            } else if (mode == 1) {
                __nv_bfloat162 lo0, lo1;
                __nv_bfloat162 hi0 = split_hi2(v00, v01, lo0);
                __nv_bfloat162 hi1 = split_hi2(v10, v11, lo1);
                *(__nv_bfloat162*)&Ch[(size_t)r * DIM + c] = hi0;
                *(__nv_bfloat162*)&Cl[(size_t)r * DIM + c] = lo0;
                *(__nv_bfloat162*)&Ch[(size_t)(r + 8) * DIM + c] = hi1;
                *(__nv_bfloat162*)&Cl[(size_t)(r + 8) * DIM + c] = lo1;
            } else {
                // VT[(b*12+h)*64+d][n], r = b*1024+n, c = h*64+d
                int b = r >> 10, n = r & 1023;
                size_t row_c0 = ((size_t)b * NHEAD + (c >> 6)) * HDIM + (c & 63);
                size_t row_c1 = ((size_t)b * NHEAD + ((c + 1) >> 6)) * HDIM + ((c + 1) & 63);
                __nv_bfloat16 h, l;
                h = __float2bfloat16(v00); l = __float2bfloat16(v00 - __bfloat162float(h));
                g_VTh[row_c0 * SEQ + n] = h; g_VTl[row_c0 * SEQ + n] = l;
                h = __float2bfloat16(v01); l = __float2bfloat16(v01 - __bfloat162float(h));
                g_VTh[row_c1 * SEQ + n] = h; g_VTl[row_c1 * SEQ + n] = l;
                h = __float2bfloat16(v10); l = __float2bfloat16(v10 - __bfloat162float(h));
                g_VTh[row_c0 * SEQ + n + 8] = h; g_VTl[row_c0 * SEQ + n + 8] = l;
                h = __float2bfloat16(v11); l = __float2bfloat16(v11 - __bfloat162float(h));
                g_VTh[row_c1 * SEQ + n + 8] = h; g_VTl[row_c1 * SEQ + n + 8] = l;
            }
        }
    }
}

// ---------------------------------------------------------------------------
// scores = 0.125 * Q @ K^T per (b,h), mma bf16x3. 128x128 tile, K=64.
// ---------------------------------------------------------------------------
__global__ __launch_bounds__(256, 1)
void scores_mma(float* __restrict__ Wt) {
    extern __shared__ char sm[];
    const int tid = threadIdx.x;
    const int lane = tid & 31;
    const int warp = tid >> 5;
    const int wm = warp >> 2, wn = warp & 3;
    const int bh = blockIdx.z;
    const int b = bh / NHEAD, h = bh - b * NHEAD;
    const size_t i0 = (size_t)blockIdx.y * 128;
    const size_t j0 = (size_t)blockIdx.x * 128;
    const uint32_t smb = smem_u32(sm);
    const __nv_bfloat16* Qh = g_Qh + (size_t)b * SEQ * DIM + h * HDIM;
    const __nv_bfloat16* Ql = g_Ql + (size_t)b * SEQ * DIM + h * HDIM;
    const __nv_bfloat16* Kh = g_Kh + (size_t)b * SEQ * DIM + h * HDIM;
    const __nv_bfloat16* Kl = g_Kl + (size_t)b * SEQ * DIM + h * HDIM;

    float acc[4][4][4];
    #pragma unroll
    for (int i = 0; i < 4; ++i)
        #pragma unroll
        for (int j = 0; j < 4; ++j)
            #pragma unroll
            for (int q = 0; q < 4; ++q) acc[i][j][q] = 0.f;

    const int r_c0 = tid >> 2, j_c0 = tid & 3;
    const int r_c1 = (tid + 256) >> 2, j_c1 = (tid + 256) & 3;

    auto issue = [&](int s, int st) {
        const int k0 = s * 32;
        const uint32_t sb = smb + st * STAGE_B;
        uint32_t d0 = sb + r_c0 * 80 + j_c0 * 16;
        CP_ASYNC16(d0,            Qh + (i0 + r_c0) * DIM + k0 + j_c0 * 8);
        CP_ASYNC16(d0 + TILE_B,   Ql + (i0 + r_c0) * DIM + k0 + j_c0 * 8);
        CP_ASYNC16(d0 + 2*TILE_B, Kh + (j0 + r_c0) * DIM + k0 + j_c0 * 8);
        CP_ASYNC16(d0 + 3*TILE_B, Kl + (j0 + r_c0) * DIM + k0 + j_c0 * 8);
        uint32_t d1 = sb + r_c1 * 80 + j_c1 * 16;
        CP_ASYNC16(d1,            Qh + (i0 + r_c1) * DIM + k0 + j_c1 * 8);
        CP_ASYNC16(d1 + TILE_B,   Ql + (i0 + r_c1) * DIM + k0 + j_c1 * 8);
        CP_ASYNC16(d1 + 2*TILE_B, Kh + (j0 + r_c1) * DIM + k0 + j_c1 * 8);
        CP_ASYNC16(d1 + 3*TILE_B, Kl + (j0 + r_c1) * DIM + k0 + j_c1 * 8);
        CP_COMMIT();
    };

    const int a_row_l = (lane & 15);
    const int a_col_l = (lane >> 4) << 3;
    const int b_row_l = (lane & 7) + ((lane >> 4) << 3);
    const int b_col_l = ((lane >> 3) & 1) << 3;

    issue(0, 0);
    for (int s = 0; s < 2; ++s) {
        if (s + 1 < 2) { issue(s + 1, 1); CP_WAIT1(); }
        else          { CP_WAIT0(); }
        __syncthreads();
        const uint32_t sb = smb + (s & 1) * STAGE_B;
        const uint32_t tAh = sb, tAl = sb + TILE_B;
        const uint32_t tBh = sb + 2 * TILE_B, tBl = sb + 3 * TILE_B;
        #pragma unroll
        for (int ks = 0; ks < 2; ++ks) {
            uint32_t ah[4][4], al[4][4], bh2[4][2], bl2[4][2];
            #pragma unroll
            for (int mi = 0; mi < 4; ++mi) {
                uint32_t off = (uint32_t)((wm * 64 + mi * 16 + a_row_l) * 80 +
                                          (ks * 16 + a_col_l) * 2);
                LDSM_X4(ah[mi][0], ah[mi][1], ah[mi][2], ah[mi][3], tAh + off);
                LDSM_X4(al[mi][0], al[mi][1], al[mi][2], al[mi][3], tAl + off);
            }
            #pragma unroll
            for (int nj = 0; nj < 2; ++nj) {
                uint32_t off = (uint32_t)((wn * 32 + nj * 16 + b_row_l) * 80 +
                                          (ks * 16 + b_col_l) * 2);
                uint32_t t0, t1, t2, t3;
                LDSM_X4(t0, t1, t2, t3, tBh + off);
                bh2[nj * 2][0] = t0; bh2[nj * 2][1] = t1;
                bh2[nj * 2 + 1][0] = t2; bh2[nj * 2 + 1][1] = t3;
                LDSM_X4(t0, t1, t2, t3, tBl + off);
                bl2[nj * 2][0] = t0; bl2[nj * 2][1] = t1;
                bl2[nj * 2 + 1][0] = t2; bl2[nj * 2 + 1][1] = t3;
            }
            #pragma unroll
            for (int mi = 0; mi < 4; ++mi)
                #pragma unroll
                for (int ni = 0; ni < 4; ++ni) {
                    MMA16816(acc[mi][ni], ah[mi], bh2[ni]);
                    MMA16816(acc[mi][ni], al[mi], bh2[ni]);
                    MMA16816(acc[mi][ni], ah[mi], bl2[ni]);
                }
        }
        __syncthreads();
    }

    float* Wb = Wt + (size_t)bh * SEQ * SEQ;
    const int mbase = (int)i0 + wm * 64;
    const int nbase = (int)j0 + wn * 32;
    #pragma unroll
    for (int mi = 0; mi < 4; ++mi) {
        #pragma unroll
        for (int ni = 0; ni < 4; ++ni) {
            int r = mbase + mi * 16 + (lane >> 2);
            int c = nbase + ni * 8 + (lane & 3) * 2;
            *(float2*)&Wb[(size_t)r * SEQ + c] =
                make_float2(acc[mi][ni][0] * 0.125f, acc[mi][ni][1] * 0.125f);
            *(float2*)&Wb[(size_t)(r + 8) * SEQ + c] =
                make_float2(acc[mi][ni][2] * 0.125f, acc[mi][ni][3] * 0.125f);
        }
    }
}

// ---------------------------------------------------------------------------
// softmax in-place + emit P as bf16 hi/lo.
// ---------------------------------------------------------------------------
__global__ void softmax_kernel(float* __restrict__ Wt) {
    size_t row = blockIdx.x;
    float* p = Wt + row * SEQ;
    int tid = threadIdx.x;
    float4 v = reinterpret_cast<float4*>(p)[tid];

    __shared__ float red[8];
    float m = fmaxf(fmaxf(v.x, v.y), fmaxf(v.z, v.w));
    #pragma unroll
    for (int o = 16; o; o >>= 1) m = fmaxf(m, __shfl_xor_sync(~0u, m, o));
    if ((tid & 31) == 0) red[tid >> 5] = m;
    __syncthreads();
    m = red[0];
    #pragma unroll
    for (int i = 1; i < 8; ++i) m = fmaxf(m, red[i]);
    __syncthreads();

    v.x = __expf(v.x - m); v.y = __expf(v.y - m);
    v.z = __expf(v.z - m); v.w = __expf(v.w - m);
    float s = v.x + v.y + v.z + v.w;
    #pragma unroll
    for (int o = 16; o; o >>= 1) s += __shfl_xor_sync(~0u, s, o);
    if ((tid & 31) == 0) red[tid >> 5] = s;
    __syncthreads();
    s = red[0];
    #pragma unroll
    for (int i = 1; i < 8; ++i) s += red[i];

    float inv = 1.0f / s;
    v.x *= inv; v.y *= inv; v.z *= inv; v.w *= inv;
    reinterpret_cast<float4*>(p)[tid] = v;

    __nv_bfloat162 lo0, lo1;
    __nv_bfloat162 hi0 = split_hi2(v.x, v.y, lo0);
    __nv_bfloat162 hi1 = split_hi2(v.z, v.w, lo1);
    size_t base2 = row * (SEQ / 2) + tid * 2;
    reinterpret_cast<__nv_bfloat162*>(g_Ph)[base2]     = hi0;
    reinterpret_cast<__nv_bfloat162*>(g_Ph)[base2 + 1] = hi1;
    reinterpret_cast<__nv_bfloat162*>(g_Pl)[base2]     = lo0;
    reinterpret_cast<__nv_bfloat162*>(g_Pl)[base2 + 1] = lo1;
}

// ---------------------------------------------------------------------------
// O = P @ V per (b,h), mma bf16x3. Block 256x64, K-slab 32 (32 slabs).
// A = P rows (stride SEQ), B = VT rows (stride SEQ). Out: Oh/Ol flat.
// ---------------------------------------------------------------------------
#define AV_ATILE 20480                 // 256*40*2
#define AV_BTILE 5120                  // 64*40*2
#define AV_STAGE (2 * AV_ATILE + 2 * AV_BTILE)   // 51200
#define AV_SMEM  (2 * AV_STAGE)                  // 102400

__global__ __launch_bounds__(256, 1)
void av_mma(const float* __restrict__ Wt) {
    extern __shared__ char sm[];
    const int tid = threadIdx.x;
    const int lane = tid & 31;
    const int warp = tid >> 5;
    const int wm = warp >> 1, wn = warp & 1;     // 4 x 2 warp grid
    const int bh = blockIdx.z;
    const int b = bh / NHEAD, h = bh - b * NHEAD;
    const size_t m0 = (size_t)blockIdx.y * 256;
    const uint32_t smb = smem_u32(sm);
    const __nv_bfloat16* Ph = g_Ph + (size_t)bh * SEQ * SEQ;
    const __nv_bfloat16* Pl = g_Pl + (size_t)bh * SEQ * SEQ;
    const __nv_bfloat16* Bh = g_VTh + (size_t)bh * HDIM * SEQ;
    const __nv_bfloat16* Bl = g_VTl + (size_t)bh * HDIM * SEQ;

    float acc[4][4][4];
    #pragma unroll
    for (int i = 0; i < 4; ++i)
        #pragma unroll
        for (int j = 0; j < 4; ++j)
            #pragma unroll
            for (int q = 0; q < 4; ++q) acc[i][j][q] = 0.f;

    auto issue = [&](int s, int st) {
        const int k0 = s * 32;
        const uint32_t sb = smb + st * AV_STAGE;
        #pragma unroll
        for (int p = 0; p < 4; ++p) {            // A: 256 rows x 4 chunks
            int idx = tid + p * 256;
            int r = idx >> 2, j = idx & 3;
            uint32_t d = sb + r * 80 + j * 16;
            CP_ASYNC16(d,            Ph + (m0 + r) * SEQ + k0 + j * 8);
            CP_ASYNC16(d + AV_ATILE, Pl + (m0 + r) * SEQ + k0 + j * 8);
        }
        {                                        // B: 64 rows x 4 chunks
            int r = tid >> 2, j = tid & 3;
            if (r < 64) {
                uint32_t d = sb + 2 * AV_ATILE + r * 80 + j * 16;
                CP_ASYNC16(d,            Bh + (size_t)r * SEQ + k0 + j * 8);
                CP_ASYNC16(d + AV_BTILE, Bl + (size_t)r * SEQ + k0 + j * 8);
            }
        }
        CP_COMMIT();
    };

    const int a_row_l = (lane & 15);
    const int a_col_l = (lane >> 4) << 3;
    const int b_row_l = (lane & 7) + ((lane >> 4) << 3);
    const int b_col_l = ((lane >> 3) & 1) << 3;

    issue(0, 0);
    for (int s = 0; s < 32; ++s) {
        if (s + 1 < 32) { issue(s + 1, (s + 1) & 1); CP_WAIT1(); }
        else           { CP_WAIT0(); }
        __syncthreads();
        const uint32_t sb = smb + (s & 1) * AV_STAGE;
        const uint32_t tAh = sb, tAl = sb + AV_ATILE;
        const uint32_t tBh = sb + 2 * AV_ATILE, tBl = tBh + AV_BTILE;
        #pragma unroll
        for (int ks = 0; ks < 2; ++ks) {
            uint32_t ah[4][4], al[4][4], bh2[4][2], bl2[4][2];
            #pragma unroll
            for (int mi = 0; mi < 4; ++mi) {
                uint32_t off = (uint32_t)((wm * 64 + mi * 16 + a_row_l) * 80 +
                                          (ks * 16 + a_col_l) * 2);
                LDSM_X4(ah[mi][0], ah[mi][1], ah[mi][2], ah[mi][3], tAh + off);
                LDSM_X4(al[mi][0], al[mi][1], al[mi][2], al[mi][3], tAl + off);
            }
            #pragma unroll
            for (int nj = 0; nj < 2; ++nj) {
                uint32_t off = (uint32_t)((wn * 32 + nj * 16 + b_row_l) * 80 +
                                          (ks * 16 + b_col_l) * 2);
                uint32_t t0, t1, t2, t3;
                LDSM_X4(t0, t1, t2, t3, tBh + off);
                bh2[nj * 2][0] = t0; bh2[nj * 2][1] = t1;
                bh2[nj * 2 + 1][0] = t2; bh2[nj * 2 + 1][1] = t3;
                LDSM_X4(t0, t1, t2, t3, tBl + off);
                bl2[nj * 2][0] = t0; bl2[nj * 2][1] = t1;
                bl2[nj * 2 + 1][0] = t2; bl2[nj * 2 + 1][1] = t3;
            }
            #pragma unroll
            for (int mi = 0; mi < 4; ++mi)
                #pragma unroll
                for (int ni = 0; ni < 4; ++ni) {
                    MMA16816(acc[mi][ni], ah[mi], bh2[ni]);
                    MMA16816(acc[mi][ni], al[mi], bh2[ni]);
                    MMA16816(acc[mi][ni], ah[mi], bl2[ni]);
                }
        }
        __syncthreads();
    }

    // epilogue -> Oh/Ol flat [8192][768], row = b*1024 + seq, col = h*64 + d
    #pragma unroll
    for (int mi = 0; mi < 4; ++mi) {
        #pragma unroll
        for (int ni = 0; ni < 4; ++ni) {
            int rl = wm * 64 + mi * 16 + (lane >> 2);       // 0..255
            int cl = wn * 32 + ni * 8 + (lane & 3) * 2;     // 0..63
            size_t r = (size_t)b * SEQ + m0 + rl;
            size_t c = h * HDIM + cl;
            __nv_bfloat162 lo0, lo1;
            __nv_bfloat162 hi0 = split_hi2(acc[mi][ni][0], acc[mi][ni][1], lo0);
            __nv_bfloat162 hi1 = split_hi2(acc[mi][ni][2], acc[mi][ni][3], lo1);
            *(__nv_bfloat162*)&g_Oh[r * DIM + c] = hi0;
            *(__nv_bfloat162*)&g_Ol[r * DIM + c] = lo0;
            *(__nv_bfloat162*)&g_Oh[(r + 8) * DIM + c] = hi1;
            *(__nv_bfloat162*)&g_Ol[(r + 8) * DIM + c] = lo1;
        }
    }
}

// ---------------------------------------------------------------------------
extern "C" void kernel_launch(void* const* d_in, const int* in_sizes, int n_in,
                              void* d_out, int out_size) {
    const float* x  = (const float*)d_in[0];
    const float* Wq = (const float*)d_in[1];
    const float* bq = (const float*)d_in[2];
    const float* Wk = (const float*)d_in[3];
    const float* bk = (const float*)d_in[4];
    const float* Wv = (const float*)d_in[5];
    const float* bv = (const float*)d_in[6];
    const float* Wo = (const float*)d_in[7];
    const float* bo = (const float*)d_in[8];

    float* out = (float*)d_out;
    float* wts = out + OUT_OFF;

    cudaFuncSetAttribute(gemm_mma_bf16x3,
                         cudaFuncAttributeMaxDynamicSharedMemorySize, GSMEM);
    cudaFuncSetAttribute(scores_mma,
                         cudaFuncAttributeMaxDynamicSharedMemorySize, GSMEM);
    cudaFuncSetAttribute(av_mma,
                         cudaFuncAttributeMaxDynamicSharedMemorySize, AV_SMEM);

    __nv_bfloat16 *Xh, *Xl, *Qh, *Ql, *Kh, *Kl, *Oh, *Ol, *WTh, *WTl;
    cudaGetSymbolAddress((void**)&Xh, g_Xh);
    cudaGetSymbolAddress((void**)&Xl, g_Xl);
    cudaGetSymbolAddress((void**)&Qh, g_Qh);
    cudaGetSymbolAddress((void**)&Ql, g_Ql);
    cudaGetSymbolAddress((void**)&Kh, g_Kh);
    cudaGetSymbolAddress((void**)&Kl, g_Kl);
    cudaGetSymbolAddress((void**)&Oh, g_Oh);
    cudaGetSymbolAddress((void**)&Ol, g_Ol);
    cudaGetSymbolAddress((void**)&WTh, g_WTh);
    cudaGetSymbolAddress((void**)&WTl, g_WTl);

    const int NELEM = MROWS * DIM;
    split_kernel<<<NELEM / 4 / 256, 256>>>(x, Xh, Xl, NELEM / 4);
    const int WT_BLK = (DIM * DIM + 255) / 256;
    splitT_kernel<<<WT_BLK, 256>>>(Wq, WTh + 0 * DIM * DIM, WTl + 0 * DIM * DIM);
    splitT_kernel<<<WT_BLK, 256>>>(Wk, WTh + 1 * DIM * DIM, WTl + 1 * DIM * DIM);
    splitT_kernel<<<WT_BLK, 256>>>(Wv, WTh + 2 * DIM * DIM, WTl + 2 * DIM * DIM);
    splitT_kernel<<<WT_BLK, 256>>>(Wo, WTh + 3 * DIM * DIM, WTl + 3 * DIM * DIM);

    dim3 gG(DIM / 128, MROWS / 128);            // (6, 64)
    gemm_mma_bf16x3<<<gG, 256, GSMEM>>>(Xh, Xl, WTh + 0 * DIM * DIM,
                                        WTl + 0 * DIM * DIM, bq,
                                        nullptr, Qh, Ql, 1);
    gemm_mma_bf16x3<<<gG, 256, GSMEM>>>(Xh, Xl, WTh + 1 * DIM * DIM,
                                        WTl + 1 * DIM * DIM, bk,
                                        nullptr, Kh, Kl, 1);
    gemm_mma_bf16x3<<<gG, 256, GSMEM>>>(Xh, Xl, WTh + 2 * DIM * DIM,
                                        WTl + 2 * DIM * DIM, bv,
                                        nullptr, nullptr, nullptr, 2);

    scores_mma<<<dim3(SEQ / 128, SEQ / 128, BH), 256, GSMEM>>>(wts);
    softmax_kernel<<<BH * SEQ, 256>>>(wts);
    av_mma<<<dim3(1, SEQ / 256, BH), 256, AV_SMEM>>>(wts);

    gemm_mma_bf16x3<<<gG, 256, GSMEM>>>(Oh, Ol, WTh + 3 * DIM * DIM,
                                        WTl + 3 * DIM * DIM, bo,
                                        out, nullptr, nullptr, 0);
}

// round 6
// speedup vs baseline: 3.9853x; 1.2080x over previous
#include <cuda_runtime.h>
#include <cuda_bf16.h>
#include <cstdint>

#define BATCH 8
#define SEQ   1024
#define DIM   768
#define NHEAD 12
#define HDIM  64
#define BH    (BATCH * NHEAD)     // 96
#define MROWS (BATCH * SEQ)       // 8192
#define OUT_OFF ((size_t)MROWS * DIM)

// ---------------- scratch (__device__ globals; no allocs allowed) ----------
__device__ __nv_bfloat16 g_Xh[MROWS * DIM];
__device__ __nv_bfloat16 g_Xl[MROWS * DIM];
__device__ __nv_bfloat16 g_Qh[MROWS * DIM];
__device__ __nv_bfloat16 g_Ql[MROWS * DIM];
__device__ __nv_bfloat16 g_Kh[MROWS * DIM];
__device__ __nv_bfloat16 g_Kl[MROWS * DIM];
__device__ __nv_bfloat16 g_VTh[BH * HDIM * SEQ];  // [bh*64+d][n]
__device__ __nv_bfloat16 g_VTl[BH * HDIM * SEQ];
__device__ __nv_bfloat16 g_Oh[MROWS * DIM];
__device__ __nv_bfloat16 g_Ol[MROWS * DIM];
__device__ __nv_bfloat16 g_WTh[4 * DIM * DIM];    // W^T hi ([n][k])
__device__ __nv_bfloat16 g_WTl[4 * DIM * DIM];

// ---------------- helpers --------------------------------------------------
__device__ __forceinline__ uint32_t smem_u32(const void* p) {
    uint32_t a;
    asm("{ .reg .u64 t; cvta.to.shared.u64 t, %1; cvt.u32.u64 %0, t; }"
        : "=r"(a) : "l"(p));
    return a;
}
#define CP_ASYNC16(sm, gp) \
    asm volatile("cp.async.cg.shared.global [%0], [%1], 16;" \
                 :: "r"(sm), "l"(gp) : "memory")
#define CP_COMMIT() asm volatile("cp.async.commit_group;" ::: "memory")
#define CP_WAIT1()  asm volatile("cp.async.wait_group 1;" ::: "memory")
#define CP_WAIT0()  asm volatile("cp.async.wait_group 0;" ::: "memory")
#define LDSM_X4(r0, r1, r2, r3, addr) \
    asm volatile("ldmatrix.sync.aligned.m8n8.x4.shared.b16 {%0,%1,%2,%3}, [%4];" \
                 : "=r"(r0), "=r"(r1), "=r"(r2), "=r"(r3) : "r"(addr))
#define MMA16816(d, a, b) \
    asm volatile("mma.sync.aligned.m16n8k16.row.col.f32.bf16.bf16.f32 " \
                 "{%0,%1,%2,%3}, {%4,%5,%6,%7}, {%8,%9}, {%0,%1,%2,%3};" \
                 : "+f"((d)[0]), "+f"((d)[1]), "+f"((d)[2]), "+f"((d)[3]) \
                 : "r"((a)[0]), "r"((a)[1]), "r"((a)[2]), "r"((a)[3]), \
                   "r"((b)[0]), "r"((b)[1]))

__device__ __forceinline__ __nv_bfloat162 split_hi2(float a, float b,
                                                    __nv_bfloat162& lo) {
    __nv_bfloat16 h0 = __float2bfloat16(a);
    __nv_bfloat16 h1 = __float2bfloat16(b);
    lo.x = __float2bfloat16(a - __bfloat162float(h0));
    lo.y = __float2bfloat16(b - __bfloat162float(h1));
    __nv_bfloat162 hi; hi.x = h0; hi.y = h1;
    return hi;
}

// ---------------------------------------------------------------------------
__global__ void split_kernel(const float* __restrict__ src,
                             __nv_bfloat16* __restrict__ hi,
                             __nv_bfloat16* __restrict__ lo, int n4) {
    int i = blockIdx.x * blockDim.x + threadIdx.x;
    if (i >= n4) return;
    float4 v = reinterpret_cast<const float4*>(src)[i];
    __nv_bfloat162 l0, l1;
    __nv_bfloat162 h0 = split_hi2(v.x, v.y, l0);
    __nv_bfloat162 h1 = split_hi2(v.z, v.w, l1);
    reinterpret_cast<__nv_bfloat162*>(hi)[2 * i]     = h0;
    reinterpret_cast<__nv_bfloat162*>(hi)[2 * i + 1] = h1;
    reinterpret_cast<__nv_bfloat162*>(lo)[2 * i]     = l0;
    reinterpret_cast<__nv_bfloat162*>(lo)[2 * i + 1] = l1;
}

// Tiled transpose+split of all 4 weights: W[k][n] -> hiT/loT[n][k].
__global__ void splitT4(const float* __restrict__ W0, const float* __restrict__ W1,
                        const float* __restrict__ W2, const float* __restrict__ W3,
                        __nv_bfloat16* __restrict__ hiT,
                        __nv_bfloat16* __restrict__ loT) {
    __shared__ float t[32][33];
    int z = blockIdx.z;
    const float* W = (z == 0) ? W0 : (z == 1) ? W1 : (z == 2) ? W2 : W3;
    size_t zoff = (size_t)z * DIM * DIM;
    int n0 = blockIdx.x * 32, k0 = blockIdx.y * 32;
    int tx = threadIdx.x, ty = threadIdx.y;           // (32, 8)
    #pragma unroll
    for (int i = 0; i < 4; ++i)
        t[ty * 4 + i][tx] = W[(size_t)(k0 + ty * 4 + i) * DIM + n0 + tx];
    __syncthreads();
    #pragma unroll
    for (int i = 0; i < 4; ++i) {
        int n = n0 + ty * 4 + i, k = k0 + tx;
        float a = t[tx][ty * 4 + i];
        __nv_bfloat16 h = __float2bfloat16(a);
        hiT[zoff + (size_t)n * DIM + k] = h;
        loT[zoff + (size_t)n * DIM + k] = __float2bfloat16(a - __bfloat162float(h));
    }
}

// ---------------------------------------------------------------------------
// mma.sync bf16x3 GEMM: 128x128x32 tiles, 8 warps (2x4), warp 64x32.
// mode 0: fp32 C + bias.  mode 1: bf16 hi/lo flat + bias.  mode 2: VT + bias.
// ---------------------------------------------------------------------------
#define TILE_B   10240
#define STAGE_B  (4 * TILE_B)
#define GSMEM    (2 * STAGE_B)         // 81920

__global__ __launch_bounds__(256, 1)
void gemm_mma_bf16x3(const __nv_bfloat16* __restrict__ Ah,
                     const __nv_bfloat16* __restrict__ Al,
                     const __nv_bfloat16* __restrict__ Bh,
                     const __nv_bfloat16* __restrict__ Bl,
                     const float* __restrict__ bias,
                     float* __restrict__ Cf,
                     __nv_bfloat16* __restrict__ Ch,
                     __nv_bfloat16* __restrict__ Cl, int mode) {
    extern __shared__ char sm[];
    const int tid = threadIdx.x;
    const int lane = tid & 31;
    const int warp = tid >> 5;
    const int wm = warp >> 2, wn = warp & 3;
    const size_t row0 = (size_t)blockIdx.y * 128;
    const size_t col0 = (size_t)blockIdx.x * 128;
    const uint32_t smb = smem_u32(sm);

    float acc[4][4][4];
    #pragma unroll
    for (int i = 0; i < 4; ++i)
        #pragma unroll
        for (int j = 0; j < 4; ++j)
            #pragma unroll
            for (int q = 0; q < 4; ++q) acc[i][j][q] = 0.f;

    const int r_c0 = tid >> 2, j_c0 = tid & 3;
    const int r_c1 = (tid + 256) >> 2, j_c1 = (tid + 256) & 3;

    auto issue = [&](int s, int st) {
        const int k0 = s * 32;
        const uint32_t sb = smb + st * STAGE_B;
        uint32_t d0 = sb + r_c0 * 80 + j_c0 * 16;
        CP_ASYNC16(d0,            Ah + (row0 + r_c0) * DIM + k0 + j_c0 * 8);
        CP_ASYNC16(d0 + TILE_B,   Al + (row0 + r_c0) * DIM + k0 + j_c0 * 8);
        CP_ASYNC16(d0 + 2*TILE_B, Bh + (col0 + r_c0) * DIM + k0 + j_c0 * 8);
        CP_ASYNC16(d0 + 3*TILE_B, Bl + (col0 + r_c0) * DIM + k0 + j_c0 * 8);
        uint32_t d1 = sb + r_c1 * 80 + j_c1 * 16;
        CP_ASYNC16(d1,            Ah + (row0 + r_c1) * DIM + k0 + j_c1 * 8);
        CP_ASYNC16(d1 + TILE_B,   Al + (row0 + r_c1) * DIM + k0 + j_c1 * 8);
        CP_ASYNC16(d1 + 2*TILE_B, Bh + (col0 + r_c1) * DIM + k0 + j_c1 * 8);
        CP_ASYNC16(d1 + 3*TILE_B, Bl + (col0 + r_c1) * DIM + k0 + j_c1 * 8);
        CP_COMMIT();
    };

    const int a_row_l = (lane & 15);
    const int a_col_l = (lane >> 4) << 3;
    const int b_row_l = (lane & 7) + ((lane >> 4) << 3);
    const int b_col_l = ((lane >> 3) & 1) << 3;

    issue(0, 0);
    for (int s = 0; s < 24; ++s) {
        if (s + 1 < 24) { issue(s + 1, (s + 1) & 1); CP_WAIT1(); }
        else           { CP_WAIT0(); }
        __syncthreads();
        const uint32_t sb = smb + (s & 1) * STAGE_B;
        const uint32_t tAh = sb, tAl = sb + TILE_B;
        const uint32_t tBh = sb + 2 * TILE_B, tBl = sb + 3 * TILE_B;
        #pragma unroll
        for (int ks = 0; ks < 2; ++ks) {
            uint32_t ah[4][4], al[4][4], bh[4][2], bl[4][2];
            #pragma unroll
            for (int mi = 0; mi < 4; ++mi) {
                uint32_t off = (uint32_t)((wm * 64 + mi * 16 + a_row_l) * 80 +
                                          (ks * 16 + a_col_l) * 2);
                LDSM_X4(ah[mi][0], ah[mi][1], ah[mi][2], ah[mi][3], tAh + off);
                LDSM_X4(al[mi][0], al[mi][1], al[mi][2], al[mi][3], tAl + off);
            }
            #pragma unroll
            for (int nj = 0; nj < 2; ++nj) {
                uint32_t off = (uint32_t)((wn * 32 + nj * 16 + b_row_l) * 80 +
                                          (ks * 16 + b_col_l) * 2);
                uint32_t t0, t1, t2, t3;
                LDSM_X4(t0, t1, t2, t3, tBh + off);
                bh[nj * 2][0] = t0; bh[nj * 2][1] = t1;
                bh[nj * 2 + 1][0] = t2; bh[nj * 2 + 1][1] = t3;
                LDSM_X4(t0, t1, t2, t3, tBl + off);
                bl[nj * 2][0] = t0; bl[nj * 2][1] = t1;
                bl[nj * 2 + 1][0] = t2; bl[nj * 2 + 1][1] = t3;
            }
            #pragma unroll
            for (int mi = 0; mi < 4; ++mi)
                #pragma unroll
                for (int ni = 0; ni < 4; ++ni) {
                    MMA16816(acc[mi][ni], ah[mi], bh[ni]);
                    MMA16816(acc[mi][ni], al[mi], bh[ni]);
                    MMA16816(acc[mi][ni], ah[mi], bl[ni]);
                }
        }
        __syncthreads();
    }

    const int mbase = (int)row0 + wm * 64;
    const int nbase = (int)col0 + wn * 32;
    #pragma unroll
    for (int mi = 0; mi < 4; ++mi) {
        #pragma unroll
        for (int ni = 0; ni < 4; ++ni) {
            int r = mbase + mi * 16 + (lane >> 2);
            int c = nbase + ni * 8 + (lane & 3) * 2;
            float b0 = bias[c], b1 = bias[c + 1];
            float v00 = acc[mi][ni][0] + b0, v01 = acc[mi][ni][1] + b1;
            float v10 = acc[mi][ni][2] + b0, v11 = acc[mi][ni][3] + b1;
            if (mode == 0) {
                *(float2*)&Cf[(size_t)r * DIM + c] = make_float2(v00, v01);
                *(float2*)&Cf[(size_t)(r + 8) * DIM + c] = make_float2(v10, v11);
            } else if (mode == 1) {
                __nv_bfloat162 lo0, lo1;
                __nv_bfloat162 hi0 = split_hi2(v00, v01, lo0);
                __nv_bfloat162 hi1 = split_hi2(v10, v11, lo1);
                *(__nv_bfloat162*)&Ch[(size_t)r * DIM + c] = hi0;
                *(__nv_bfloat162*)&Cl[(size_t)r * DIM + c] = lo0;
                *(__nv_bfloat162*)&Ch[(size_t)(r + 8) * DIM + c] = hi1;
                *(__nv_bfloat162*)&Cl[(size_t)(r + 8) * DIM + c] = lo1;
            } else {
                int b = r >> 10, n = r & 1023;
                size_t row_c0 = ((size_t)b * NHEAD + (c >> 6)) * HDIM + (c & 63);
                size_t row_c1 = ((size_t)b * NHEAD + ((c + 1) >> 6)) * HDIM + ((c + 1) & 63);
                __nv_bfloat16 h, l;
                h = __float2bfloat16(v00); l = __float2bfloat16(v00 - __bfloat162float(h));
                g_VTh[row_c0 * SEQ + n] = h; g_VTl[row_c0 * SEQ + n] = l;
                h = __float2bfloat16(v01); l = __float2bfloat16(v01 - __bfloat162float(h));
                g_VTh[row_c1 * SEQ + n] = h; g_VTl[row_c1 * SEQ + n] = l;
                h = __float2bfloat16(v10); l = __float2bfloat16(v10 - __bfloat162float(h));
                g_VTh[row_c0 * SEQ + n + 8] = h; g_VTl[row_c0 * SEQ + n + 8] = l;
                h = __float2bfloat16(v11); l = __float2bfloat16(v11 - __bfloat162float(h));
                g_VTh[row_c1 * SEQ + n + 8] = h; g_VTl[row_c1 * SEQ + n + 8] = l;
            }
        }
    }
}

// ---------------------------------------------------------------------------
// Fused scores + softmax: per block, 32 rows x 1024 cols for one (b,h).
// S = 0.125*Q@K^T accumulated in registers (8 chunks of 128 cols), then
// row softmax via shfl + smem partials; single fp32 write of weights.
// ---------------------------------------------------------------------------
#define KST 72                       // K/Q smem row stride in halves (144 B)
#define AF_QSZ (32 * KST * 2)        // 4608 B per component
#define AF_KSZ (128 * KST * 2)       // 18432 B per component per buffer
#define AF_Q0  0
#define AF_Q1  AF_QSZ
#define AF_K0  (2 * AF_QSZ)          // buf0 hi, buf0 lo, buf1 hi, buf1 lo
#define AF_RED (AF_K0 + 4 * AF_KSZ)  // 83968 total with 2x512B red arrays
#define AF_SMEM (AF_RED + 1024)

__global__ __launch_bounds__(256, 1)
void attn_fused(float* __restrict__ Wt) {
    extern __shared__ char sm[];
    const uint32_t smb = smem_u32(sm);
    float* red_max = (float*)(sm + AF_RED);         // [32][4]
    float* red_sum = (float*)(sm + AF_RED + 512);   // [32][4]
    const int tid = threadIdx.x;
    const int lane = tid & 31;
    const int warp = tid >> 5;
    const int wm = warp >> 2, wn = warp & 3;
    const int bh = blockIdx.y;
    const int b = bh / NHEAD, h = bh - b * NHEAD;
    const size_t i0 = (size_t)blockIdx.x * 32;
    const __nv_bfloat16* Qh = g_Qh + ((size_t)b * SEQ) * DIM + h * HDIM;
    const __nv_bfloat16* Ql = g_Ql + ((size_t)b * SEQ) * DIM + h * HDIM;
    const __nv_bfloat16* Kh = g_Kh + ((size_t)b * SEQ) * DIM + h * HDIM;
    const __nv_bfloat16* Kl = g_Kl + ((size_t)b * SEQ) * DIM + h * HDIM;

    float acc[8][4][4];
    #pragma unroll
    for (int c = 0; c < 8; ++c)
        #pragma unroll
        for (int j = 0; j < 4; ++j)
            #pragma unroll
            for (int q = 0; q < 4; ++q) acc[c][j][q] = 0.f;

    // Q: 32 rows x 128B (hi,lo); one 16B chunk per thread per component
    {
        int r = tid >> 3, j = tid & 7;
        uint32_t d = smb + AF_Q0 + r * 144 + j * 16;
        CP_ASYNC16(d,          Qh + (i0 + r) * DIM + j * 8);
        CP_ASYNC16(d + AF_QSZ, Ql + (i0 + r) * DIM + j * 8);
        // K chunk 0
        #pragma unroll
        for (int p = 0; p < 4; ++p) {
            int idx = tid + p * 256;
            int kr = idx >> 3, kj = idx & 7;
            uint32_t kd = smb + AF_K0 + kr * 144 + kj * 16;
            CP_ASYNC16(kd,          Kh + (size_t)kr * DIM + kj * 8);
            CP_ASYNC16(kd + AF_KSZ, Kl + (size_t)kr * DIM + kj * 8);
        }
        CP_COMMIT();
        // K chunk 1
        #pragma unroll
        for (int p = 0; p < 4; ++p) {
            int idx = tid + p * 256;
            int kr = idx >> 3, kj = idx & 7;
            uint32_t kd = smb + AF_K0 + 2 * AF_KSZ + kr * 144 + kj * 16;
            CP_ASYNC16(kd,          Kh + (size_t)(128 + kr) * DIM + kj * 8);
            CP_ASYNC16(kd + AF_KSZ, Kl + (size_t)(128 + kr) * DIM + kj * 8);
        }
        CP_COMMIT();
    }

    const int a_row_l = (lane & 15);
    const int a_col_l = (lane >> 4) << 3;
    const int b_row_l = (lane & 7) + ((lane >> 4) << 3);
    const int b_col_l = ((lane >> 3) & 1) << 3;

    uint32_t qh[4][4], ql[4][4];
    bool qloaded = false;

    for (int c = 0; c < 8; ++c) {
        if (c < 7) CP_WAIT1(); else CP_WAIT0();
        __syncthreads();
        if (!qloaded) {
            #pragma unroll
            for (int ks = 0; ks < 4; ++ks) {
                uint32_t off = (uint32_t)((wm * 16 + a_row_l) * 144 +
                                          (ks * 16 + a_col_l) * 2);
                LDSM_X4(qh[ks][0], qh[ks][1], qh[ks][2], qh[ks][3],
                        smb + AF_Q0 + off);
                LDSM_X4(ql[ks][0], ql[ks][1], ql[ks][2], ql[ks][3],
                        smb + AF_Q1 + off);
            }
            qloaded = true;
        }
        const uint32_t kb = smb + AF_K0 + (c & 1) * 2 * AF_KSZ;
        #pragma unroll
        for (int ks = 0; ks < 4; ++ks) {
            uint32_t bh2[4][2], bl2[4][2];
            #pragma unroll
            for (int nj = 0; nj < 2; ++nj) {
                uint32_t off = (uint32_t)((wn * 32 + nj * 16 + b_row_l) * 144 +
                                          (ks * 16 + b_col_l) * 2);
                uint32_t t0, t1, t2, t3;
                LDSM_X4(t0, t1, t2, t3, kb + off);
                bh2[nj * 2][0] = t0; bh2[nj * 2][1] = t1;
                bh2[nj * 2 + 1][0] = t2; bh2[nj * 2 + 1][1] = t3;
                LDSM_X4(t0, t1, t2, t3, kb + AF_KSZ + off);
                bl2[nj * 2][0] = t0; bl2[nj * 2][1] = t1;
                bl2[nj * 2 + 1][0] = t2; bl2[nj * 2 + 1][1] = t3;
            }
            #pragma unroll
            for (int ni = 0; ni < 4; ++ni) {
                MMA16816(acc[c][ni], qh[ks], bh2[ni]);
                MMA16816(acc[c][ni], ql[ks], bh2[ni]);
                MMA16816(acc[c][ni], qh[ks], bl2[ni]);
            }
        }
        __syncthreads();
        if (c + 2 < 8) {
            const uint32_t kd0 = smb + AF_K0 + (c & 1) * 2 * AF_KSZ;
            const size_t j0n = (size_t)(c + 2) * 128;
            #pragma unroll
            for (int p = 0; p < 4; ++p) {
                int idx = tid + p * 256;
                int kr = idx >> 3, kj = idx & 7;
                uint32_t kd = kd0 + kr * 144 + kj * 16;
                CP_ASYNC16(kd,          Kh + (j0n + kr) * DIM + kj * 8);
                CP_ASYNC16(kd + AF_KSZ, Kl + (j0n + kr) * DIM + kj * 8);
            }
            CP_COMMIT();
        }
    }

    // scale by 0.125
    #pragma unroll
    for (int c = 0; c < 8; ++c)
        #pragma unroll
        for (int j = 0; j < 4; ++j)
            #pragma unroll
            for (int q = 0; q < 4; ++q) acc[c][j][q] *= 0.125f;

    const int R0 = wm * 16 + (lane >> 2);     // local rows
    const int R1 = R0 + 8;

    // row max (values [0],[1] -> R0; [2],[3] -> R1)
    float m0 = -1e30f, m1 = -1e30f;
    #pragma unroll
    for (int c = 0; c < 8; ++c)
        #pragma unroll
        for (int j = 0; j < 4; ++j) {
            m0 = fmaxf(m0, fmaxf(acc[c][j][0], acc[c][j][1]));
            m1 = fmaxf(m1, fmaxf(acc[c][j][2], acc[c][j][3]));
        }
    m0 = fmaxf(m0, __shfl_xor_sync(~0u, m0, 1));
    m0 = fmaxf(m0, __shfl_xor_sync(~0u, m0, 2));
    m1 = fmaxf(m1, __shfl_xor_sync(~0u, m1, 1));
    m1 = fmaxf(m1, __shfl_xor_sync(~0u, m1, 2));
    if ((lane & 3) == 0) {
        red_max[R0 * 4 + wn] = m0;
        red_max[R1 * 4 + wn] = m1;
    }
    __syncthreads();
    m0 = fmaxf(fmaxf(red_max[R0 * 4 + 0], red_max[R0 * 4 + 1]),
               fmaxf(red_max[R0 * 4 + 2], red_max[R0 * 4 + 3]));
    m1 = fmaxf(fmaxf(red_max[R1 * 4 + 0], red_max[R1 * 4 + 1]),
               fmaxf(red_max[R1 * 4 + 2], red_max[R1 * 4 + 3]));

    // exp + row sum
    float s0 = 0.f, s1 = 0.f;
    #pragma unroll
    for (int c = 0; c < 8; ++c)
        #pragma unroll
        for (int j = 0; j < 4; ++j) {
            acc[c][j][0] = __expf(acc[c][j][0] - m0);
            acc[c][j][1] = __expf(acc[c][j][1] - m0);
            acc[c][j][2] = __expf(acc[c][j][2] - m1);
            acc[c][j][3] = __expf(acc[c][j][3] - m1);
            s0 += acc[c][j][0] + acc[c][j][1];
            s1 += acc[c][j][2] + acc[c][j][3];
        }
    s0 += __shfl_xor_sync(~0u, s0, 1);
    s0 += __shfl_xor_sync(~0u, s0, 2);
    s1 += __shfl_xor_sync(~0u, s1, 1);
    s1 += __shfl_xor_sync(~0u, s1, 2);
    if ((lane & 3) == 0) {
        red_sum[R0 * 4 + wn] = s0;
        red_sum[R1 * 4 + wn] = s1;
    }
    __syncthreads();
    s0 = red_sum[R0 * 4 + 0] + red_sum[R0 * 4 + 1] +
         red_sum[R0 * 4 + 2] + red_sum[R0 * 4 + 3];
    s1 = red_sum[R1 * 4 + 0] + red_sum[R1 * 4 + 1] +
         red_sum[R1 * 4 + 2] + red_sum[R1 * 4 + 3];
    float inv0 = 1.0f / s0, inv1 = 1.0f / s1;

    float* Wb = Wt + ((size_t)bh * SEQ + i0) * SEQ;
    #pragma unroll
    for (int c = 0; c < 8; ++c)
        #pragma unroll
        for (int j = 0; j < 4; ++j) {
            int col = c * 128 + wn * 32 + j * 8 + (lane & 3) * 2;
            *(float2*)&Wb[(size_t)R0 * SEQ + col] =
                make_float2(acc[c][j][0] * inv0, acc[c][j][1] * inv0);
            *(float2*)&Wb[(size_t)R1 * SEQ + col] =
                make_float2(acc[c][j][2] * inv1, acc[c][j][3] * inv1);
        }
}

// ---------------------------------------------------------------------------
// O = P @ V per (b,h). P read as fp32 from the weights region; converted to
// bf16 hi/lo in-kernel (LDG->regs->split->STS pipeline). B = VT via cp.async.
// ---------------------------------------------------------------------------
#define AV_ATILE 20480                 // 256*40*2
#define AV_BTILE 5120                  // 64*40*2
#define AV_ASTG  (2 * AV_ATILE)        // hi+lo per stage
#define AV_BSTG  (2 * AV_BTILE)
#define AV_B0    (2 * AV_ASTG)         // B buffers after 2 A stages
#define AV_SMEM  (2 * AV_ASTG + 2 * AV_BSTG)   // 102400

__global__ __launch_bounds__(256, 1)
void av_mma(const float* __restrict__ Wt) {
    extern __shared__ char sm[];
    const int tid = threadIdx.x;
    const int lane = tid & 31;
    const int warp = tid >> 5;
    const int wm = warp >> 1, wn = warp & 1;     // 4 x 2 warp grid
    const int bh = blockIdx.z;
    const int b = bh / NHEAD, h = bh - b * NHEAD;
    const size_t m0 = (size_t)blockIdx.y * 256;
    const uint32_t smb = smem_u32(sm);
    const float* P = Wt + ((size_t)bh * SEQ + m0) * SEQ;
    const __nv_bfloat16* Bh = g_VTh + (size_t)bh * HDIM * SEQ;
    const __nv_bfloat16* Bl = g_VTl + (size_t)bh * HDIM * SEQ;

    float acc[4][4][4];
    #pragma unroll
    for (int i = 0; i < 4; ++i)
        #pragma unroll
        for (int j = 0; j < 4; ++j)
            #pragma unroll
            for (int q = 0; q < 4; ++q) acc[i][j][q] = 0.f;

    const int ar = tid >> 3, aj = tid & 7;       // A load: row ar+32g, col aj*4

    auto issueB = [&](int s, int st) {
        const int k0 = s * 32;
        int r = tid >> 2, j = tid & 3;
        uint32_t d = smb + AV_B0 + st * AV_BSTG + r * 80 + j * 16;
        CP_ASYNC16(d,            Bh + (size_t)r * SEQ + k0 + j * 8);
        CP_ASYNC16(d + AV_BTILE, Bl + (size_t)r * SEQ + k0 + j * 8);
        CP_COMMIT();
    };

    float4 areg[8];
    auto ldgA = [&](int s) {
        const int k0 = s * 32;
        #pragma unroll
        for (int g = 0; g < 8; ++g)
            areg[g] = *(const float4*)&P[(size_t)(ar + 32 * g) * SEQ + k0 + aj * 4];
    };
    auto stsA = [&](int st) {
        const uint32_t ab = smb + st * AV_ASTG;
        #pragma unroll
        for (int g = 0; g < 8; ++g) {
            float4 v = areg[g];
            __nv_bfloat162 lo0, lo1;
            __nv_bfloat162 hi0 = split_hi2(v.x, v.y, lo0);
            __nv_bfloat162 hi1 = split_hi2(v.z, v.w, lo1);
            uint32_t d = ab + (ar + 32 * g) * 80 + aj * 8;
            *(__nv_bfloat162*)(uintptr_t)(uint64_t)0;  // (placeholder removed below)
            asm volatile("st.shared.v2.b32 [%0], {%1, %2};" :: "r"(d),
                         "r"(*(uint32_t*)&hi0), "r"(*(uint32_t*)&lo0) : "memory");
        }
    };
    (void)stsA;   // not used; explicit code below

    const int a_row_l = (lane & 15);
    const int a_col_l = (lane >> 4) << 3;
    const int b_row_l = (lane & 7) + ((lane >> 4) << 3);
    const int b_col_l = ((lane >> 3) & 1) << 3;

    issueB(0, 0);
    issueB(1, 1);
    ldgA(0);
    for (int s = 0; s < 32; ++s) {
        // store A slab s (from regs) into stage s&1
        {
            const uint32_t ab = smb + (s & 1) * AV_ASTG;
            #pragma unroll
            for (int g = 0; g < 8; ++g) {
                float4 v = areg[g];
                __nv_bfloat162 lo0, lo1;
                __nv_bfloat162 hi0 = split_hi2(v.x, v.y, lo0);
                __nv_bfloat162 hi1 = split_hi2(v.z, v.w, lo1);
                uint32_t d = ab + (ar + 32 * g) * 80 + aj * 8;
                *(__nv_bfloat162*)(sm + (d - smb)) = hi0;
                *(__nv_bfloat162*)(sm + (d - smb) + 4) = hi1;
                *(__nv_bfloat162*)(sm + (d - smb) + AV_ATILE) = lo0;
                *(__nv_bfloat162*)(sm + (d - smb) + AV_ATILE + 4) = lo1;
            }
        }
        if (s < 31) CP_WAIT1(); else CP_WAIT0();
        __syncthreads();
        if (s + 1 < 32) ldgA(s + 1);             // overlap LDG with compute

        const uint32_t ab = smb + (s & 1) * AV_ASTG;
        const uint32_t tAh = ab, tAl = ab + AV_ATILE;
        const uint32_t bb = smb + AV_B0 + (s & 1) * AV_BSTG;
        const uint32_t tBh = bb, tBl = bb + AV_BTILE;
        #pragma unroll
        for (int ks = 0; ks < 2; ++ks) {
            uint32_t ah[4][4], al[4][4], bh2[4][2], bl2[4][2];
            #pragma unroll
            for (int mi = 0; mi < 4; ++mi) {
                uint32_t off = (uint32_t)((wm * 64 + mi * 16 + a_row_l) * 80 +
                                          (ks * 16 + a_col_l) * 2);
                LDSM_X4(ah[mi][0], ah[mi][1], ah[mi][2], ah[mi][3], tAh + off);
                LDSM_X4(al[mi][0], al[mi][1], al[mi][2], al[mi][3], tAl + off);
            }
            #pragma unroll
            for (int nj = 0; nj < 2; ++nj) {
                uint32_t off = (uint32_t)((wn * 32 + nj * 16 + b_row_l) * 80 +
                                          (ks * 16 + b_col_l) * 2);
                uint32_t t0, t1, t2, t3;
                LDSM_X4(t0, t1, t2, t3, tBh + off);
                bh2[nj * 2][0] = t0; bh2[nj * 2][1] = t1;
                bh2[nj * 2 + 1][0] = t2; bh2[nj * 2 + 1][1] = t3;
                LDSM_X4(t0, t1, t2, t3, tBl + off);
                bl2[nj * 2][0] = t0; bl2[nj * 2][1] = t1;
                bl2[nj * 2 + 1][0] = t2; bl2[nj * 2 + 1][1] = t3;
            }
            #pragma unroll
            for (int mi = 0; mi < 4; ++mi)
                #pragma unroll
                for (int ni = 0; ni < 4; ++ni) {
                    MMA16816(acc[mi][ni], ah[mi], bh2[ni]);
                    MMA16816(acc[mi][ni], al[mi], bh2[ni]);
                    MMA16816(acc[mi][ni], ah[mi], bl2[ni]);
                }
        }
        __syncthreads();
        if (s + 2 < 32) issueB(s + 2, (s) & 1);
    }

    #pragma unroll
    for (int mi = 0; mi < 4; ++mi) {
        #pragma unroll
        for (int ni = 0; ni < 4; ++ni) {
            int rl = wm * 64 + mi * 16 + (lane >> 2);
            int cl = wn * 32 + ni * 8 + (lane & 3) * 2;
            size_t r = (size_t)b * SEQ + m0 + rl;
            size_t c = h * HDIM + cl;
            __nv_bfloat162 lo0, lo1;
            __nv_bfloat162 hi0 = split_hi2(acc[mi][ni][0], acc[mi][ni][1], lo0);
            __nv_bfloat162 hi1 = split_hi2(acc[mi][ni][2], acc[mi][ni][3], lo1);
            *(__nv_bfloat162*)&g_Oh[r * DIM + c] = hi0;
            *(__nv_bfloat162*)&g_Ol[r * DIM + c] = lo0;
            *(__nv_bfloat162*)&g_Oh[(r + 8) * DIM + c] = hi1;
            *(__nv_bfloat162*)&g_Ol[(r + 8) * DIM + c] = lo1;
        }
    }
}

// ---------------------------------------------------------------------------
extern "C" void kernel_launch(void* const* d_in, const int* in_sizes, int n_in,
                              void* d_out, int out_size) {
    const float* x  = (const float*)d_in[0];
    const float* Wq = (const float*)d_in[1];
    const float* bq = (const float*)d_in[2];
    const float* Wk = (const float*)d_in[3];
    const float* bk = (const float*)d_in[4];
    const float* Wv = (const float*)d_in[5];
    const float* bv = (const float*)d_in[6];
    const float* Wo = (const float*)d_in[7];
    const float* bo = (const float*)d_in[8];

    float* out = (float*)d_out;
    float* wts = out + OUT_OFF;

    cudaFuncSetAttribute(gemm_mma_bf16x3,
                         cudaFuncAttributeMaxDynamicSharedMemorySize, GSMEM);
    cudaFuncSetAttribute(attn_fused,
                         cudaFuncAttributeMaxDynamicSharedMemorySize, AF_SMEM);
    cudaFuncSetAttribute(av_mma,
                         cudaFuncAttributeMaxDynamicSharedMemorySize, AV_SMEM);

    __nv_bfloat16 *Xh, *Xl, *Qh, *Ql, *Kh, *Kl, *Oh, *Ol, *WTh, *WTl;
    cudaGetSymbolAddress((void**)&Xh, g_Xh);
    cudaGetSymbolAddress((void**)&Xl, g_Xl);
    cudaGetSymbolAddress((void**)&Qh, g_Qh);
    cudaGetSymbolAddress((void**)&Ql, g_Ql);
    cudaGetSymbolAddress((void**)&Kh, g_Kh);
    cudaGetSymbolAddress((void**)&Kl, g_Kl);
    cudaGetSymbolAddress((void**)&Oh, g_Oh);
    cudaGetSymbolAddress((void**)&Ol, g_Ol);
    cudaGetSymbolAddress((void**)&WTh, g_WTh);
    cudaGetSymbolAddress((void**)&WTl, g_WTl);

    const int NELEM = MROWS * DIM;
    split_kernel<<<NELEM / 4 / 256, 256>>>(x, Xh, Xl, NELEM / 4);
    splitT4<<<dim3(DIM / 32, DIM / 32, 4), dim3(32, 8)>>>(Wq, Wk, Wv, Wo,
                                                          WTh, WTl);

    dim3 gG(DIM / 128, MROWS / 128);            // (6, 64)
    gemm_mma_bf16x3<<<gG, 256, GSMEM>>>(Xh, Xl, WTh + 0 * DIM * DIM,
                                        WTl + 0 * DIM * DIM, bq,
                                        nullptr, Qh, Ql, 1);
    gemm_mma_bf16x3<<<gG, 256, GSMEM>>>(Xh, Xl, WTh + 1 * DIM * DIM,
                                        WTl + 1 * DIM * DIM, bk,
                                        nullptr, Kh, Kl, 1);
    gemm_mma_bf16x3<<<gG, 256, GSMEM>>>(Xh, Xl, WTh + 2 * DIM * DIM,
                                        WTl + 2 * DIM * DIM, bv,
                                        nullptr, nullptr, nullptr, 2);

    attn_fused<<<dim3(SEQ / 32, BH), 256, AF_SMEM>>>(wts);
    av_mma<<<dim3(1, SEQ / 256, BH), 256, AV_SMEM>>>(wts);

    gemm_mma_bf16x3<<<gG, 256, GSMEM>>>(Oh, Ol, WTh + 3 * DIM * DIM,
                                        WTl + 3 * DIM * DIM, bo,
                                        out, nullptr, nullptr, 0);
}

// round 8
// speedup vs baseline: 4.0877x; 1.0257x over previous
#include <cuda_runtime.h>
#include <cuda_bf16.h>
#include <cstdint>

#define BATCH 8
#define SEQ   1024
#define DIM   768
#define NHEAD 12
#define HDIM  64
#define BH    (BATCH * NHEAD)     // 96
#define MROWS (BATCH * SEQ)       // 8192
#define OUT_OFF ((size_t)MROWS * DIM)

// ---------------- scratch (__device__ globals; no allocs allowed) ----------
__device__ __nv_bfloat16 g_Xh[MROWS * DIM];
__device__ __nv_bfloat16 g_Xl[MROWS * DIM];
__device__ __nv_bfloat16 g_Qh[MROWS * DIM];
__device__ __nv_bfloat16 g_Ql[MROWS * DIM];
__device__ __nv_bfloat16 g_Kh[MROWS * DIM];
__device__ __nv_bfloat16 g_Kl[MROWS * DIM];
__device__ __nv_bfloat16 g_VTh[BH * HDIM * SEQ];  // [bh*64+d][n]
__device__ __nv_bfloat16 g_VTl[BH * HDIM * SEQ];
__device__ __nv_bfloat16 g_Oh[MROWS * DIM];
__device__ __nv_bfloat16 g_Ol[MROWS * DIM];
__device__ __nv_bfloat16 g_WTh[4 * DIM * DIM];    // W^T hi: [q;k;v;o] rows
__device__ __nv_bfloat16 g_WTl[4 * DIM * DIM];

// ---------------- helpers --------------------------------------------------
__device__ __forceinline__ uint32_t smem_u32(const void* p) {
    uint32_t a;
    asm("{ .reg .u64 t; cvta.to.shared.u64 t, %1; cvt.u32.u64 %0, t; }"
        : "=r"(a) : "l"(p));
    return a;
}
#define CP_ASYNC16(sm, gp) \
    asm volatile("cp.async.cg.shared.global [%0], [%1], 16;" \
                 :: "r"(sm), "l"(gp) : "memory")
#define CP_COMMIT() asm volatile("cp.async.commit_group;" ::: "memory")
#define CP_WAIT2()  asm volatile("cp.async.wait_group 2;" ::: "memory")
#define CP_WAIT1()  asm volatile("cp.async.wait_group 1;" ::: "memory")
#define CP_WAIT0()  asm volatile("cp.async.wait_group 0;" ::: "memory")
#define LDSM_X4(r0, r1, r2, r3, addr) \
    asm volatile("ldmatrix.sync.aligned.m8n8.x4.shared.b16 {%0,%1,%2,%3}, [%4];" \
                 : "=r"(r0), "=r"(r1), "=r"(r2), "=r"(r3) : "r"(addr))
#define MMA16816(d, a, b) \
    asm volatile("mma.sync.aligned.m16n8k16.row.col.f32.bf16.bf16.f32 " \
                 "{%0,%1,%2,%3}, {%4,%5,%6,%7}, {%8,%9}, {%0,%1,%2,%3};" \
                 : "+f"((d)[0]), "+f"((d)[1]), "+f"((d)[2]), "+f"((d)[3]) \
                 : "r"((a)[0]), "r"((a)[1]), "r"((a)[2]), "r"((a)[3]), \
                   "r"((b)[0]), "r"((b)[1]))

__device__ __forceinline__ __nv_bfloat162 split_hi2(float a, float b,
                                                    __nv_bfloat162& lo) {
    __nv_bfloat16 h0 = __float2bfloat16(a);
    __nv_bfloat16 h1 = __float2bfloat16(b);
    lo.x = __float2bfloat16(a - __bfloat162float(h0));
    lo.y = __float2bfloat16(b - __bfloat162float(h1));
    __nv_bfloat162 hi; hi.x = h0; hi.y = h1;
    return hi;
}

// ---------------------------------------------------------------------------
__global__ void split_kernel(const float* __restrict__ src,
                             __nv_bfloat16* __restrict__ hi,
                             __nv_bfloat16* __restrict__ lo, int n4) {
    int i = blockIdx.x * blockDim.x + threadIdx.x;
    if (i >= n4) return;
    float4 v = reinterpret_cast<const float4*>(src)[i];
    __nv_bfloat162 l0, l1;
    __nv_bfloat162 h0 = split_hi2(v.x, v.y, l0);
    __nv_bfloat162 h1 = split_hi2(v.z, v.w, l1);
    reinterpret_cast<__nv_bfloat162*>(hi)[2 * i]     = h0;
    reinterpret_cast<__nv_bfloat162*>(hi)[2 * i + 1] = h1;
    reinterpret_cast<__nv_bfloat162*>(lo)[2 * i]     = l0;
    reinterpret_cast<__nv_bfloat162*>(lo)[2 * i + 1] = l1;
}

__global__ void splitT4(const float* __restrict__ W0, const float* __restrict__ W1,
                        const float* __restrict__ W2, const float* __restrict__ W3,
                        __nv_bfloat16* __restrict__ hiT,
                        __nv_bfloat16* __restrict__ loT) {
    __shared__ float t[32][33];
    int z = blockIdx.z;
    const float* W = (z == 0) ? W0 : (z == 1) ? W1 : (z == 2) ? W2 : W3;
    size_t zoff = (size_t)z * DIM * DIM;
    int n0 = blockIdx.x * 32, k0 = blockIdx.y * 32;
    int tx = threadIdx.x, ty = threadIdx.y;           // (32, 8)
    #pragma unroll
    for (int i = 0; i < 4; ++i)
        t[ty * 4 + i][tx] = W[(size_t)(k0 + ty * 4 + i) * DIM + n0 + tx];
    __syncthreads();
    #pragma unroll
    for (int i = 0; i < 4; ++i) {
        int n = n0 + ty * 4 + i, k = k0 + tx;
        float a = t[tx][ty * 4 + i];
        __nv_bfloat16 h = __float2bfloat16(a);
        hiT[zoff + (size_t)n * DIM + k] = h;
        loT[zoff + (size_t)n * DIM + k] = __float2bfloat16(a - __bfloat162float(h));
    }
}

// ---------------------------------------------------------------------------
// Shared mainloop fragment macros (128x128x32 tile, 8 warps 2x4, 3-stage).
// ---------------------------------------------------------------------------
#define TILE_B   10240
#define STAGE_B  (4 * TILE_B)          // Ah, Al, Bh, Bl
#define GSMEM3   (3 * STAGE_B)         // 122880

// ---------------------------------------------------------------------------
// Fused QKV GEMM: C[8192 x 2304] = X @ [Wq;Wk;Wv]^T + bias, epilogue routes
// to Qh/Ql, Kh/Kl (flat) or VT (transposed). grid (18, 64).
// ---------------------------------------------------------------------------
__global__ __launch_bounds__(256, 1)
void gemm_qkv(const float* __restrict__ bq, const float* __restrict__ bk,
              const float* __restrict__ bv) {
    extern __shared__ char sm[];
    const int tid = threadIdx.x;
    const int lane = tid & 31;
    const int warp = tid >> 5;
    const int wm = warp >> 2, wn = warp & 3;
    const size_t row0 = (size_t)blockIdx.y * 128;
    const int bx = blockIdx.x;
    const int sel = bx / 6;                       // 0=Q 1=K 2=V
    const size_t col0g = (size_t)bx * 128;        // row in [Wq;Wk;Wv]^T
    const int col0l = (bx - sel * 6) * 128;       // 0..640
    const uint32_t smb = smem_u32(sm);
    const float* bias = (sel == 0) ? bq : (sel == 1) ? bk : bv;

    float acc[4][4][4];
    #pragma unroll
    for (int i = 0; i < 4; ++i)
        #pragma unroll
        for (int j = 0; j < 4; ++j)
            #pragma unroll
            for (int q = 0; q < 4; ++q) acc[i][j][q] = 0.f;

    const int r_c0 = tid >> 2, j_c0 = tid & 3;
    const int r_c1 = (tid + 256) >> 2, j_c1 = (tid + 256) & 3;

    auto issue = [&](int s, int st) {
        const int k0 = s * 32;
        const uint32_t sb = smb + st * STAGE_B;
        uint32_t d0 = sb + r_c0 * 80 + j_c0 * 16;
        CP_ASYNC16(d0,            g_Xh + (row0 + r_c0) * DIM + k0 + j_c0 * 8);
        CP_ASYNC16(d0 + TILE_B,   g_Xl + (row0 + r_c0) * DIM + k0 + j_c0 * 8);
        CP_ASYNC16(d0 + 2*TILE_B, g_WTh + (col0g + r_c0) * DIM + k0 + j_c0 * 8);
        CP_ASYNC16(d0 + 3*TILE_B, g_WTl + (col0g + r_c0) * DIM + k0 + j_c0 * 8);
        uint32_t d1 = sb + r_c1 * 80 + j_c1 * 16;
        CP_ASYNC16(d1,            g_Xh + (row0 + r_c1) * DIM + k0 + j_c1 * 8);
        CP_ASYNC16(d1 + TILE_B,   g_Xl + (row0 + r_c1) * DIM + k0 + j_c1 * 8);
        CP_ASYNC16(d1 + 2*TILE_B, g_WTh + (col0g + r_c1) * DIM + k0 + j_c1 * 8);
        CP_ASYNC16(d1 + 3*TILE_B, g_WTl + (col0g + r_c1) * DIM + k0 + j_c1 * 8);
        CP_COMMIT();
    };

    const int a_row_l = (lane & 15);
    const int a_col_l = (lane >> 4) << 3;
    const int b_row_l = (lane & 7) + ((lane >> 4) << 3);
    const int b_col_l = ((lane >> 3) & 1) << 3;

    issue(0, 0); issue(1, 1);
    for (int s = 0; s < 24; ++s) {
        if (s + 2 < 24) { issue(s + 2, (s + 2) % 3); CP_WAIT2(); }
        else if (s + 1 < 24) CP_WAIT1();
        else CP_WAIT0();
        __syncthreads();
        const uint32_t sb = smb + (s % 3) * STAGE_B;
        const uint32_t tAh = sb, tAl = sb + TILE_B;
        const uint32_t tBh = sb + 2 * TILE_B, tBl = sb + 3 * TILE_B;
        #pragma unroll
        for (int ks = 0; ks < 2; ++ks) {
            uint32_t ah[4][4], al[4][4], bh[4][2], bl[4][2];
            #pragma unroll
            for (int mi = 0; mi < 4; ++mi) {
                uint32_t off = (uint32_t)((wm * 64 + mi * 16 + a_row_l) * 80 +
                                          (ks * 16 + a_col_l) * 2);
                LDSM_X4(ah[mi][0], ah[mi][1], ah[mi][2], ah[mi][3], tAh + off);
                LDSM_X4(al[mi][0], al[mi][1], al[mi][2], al[mi][3], tAl + off);
            }
            #pragma unroll
            for (int nj = 0; nj < 2; ++nj) {
                uint32_t off = (uint32_t)((wn * 32 + nj * 16 + b_row_l) * 80 +
                                          (ks * 16 + b_col_l) * 2);
                uint32_t t0, t1, t2, t3;
                LDSM_X4(t0, t1, t2, t3, tBh + off);
                bh[nj * 2][0] = t0; bh[nj * 2][1] = t1;
                bh[nj * 2 + 1][0] = t2; bh[nj * 2 + 1][1] = t3;
                LDSM_X4(t0, t1, t2, t3, tBl + off);
                bl[nj * 2][0] = t0; bl[nj * 2][1] = t1;
                bl[nj * 2 + 1][0] = t2; bl[nj * 2 + 1][1] = t3;
            }
            #pragma unroll
            for (int mi = 0; mi < 4; ++mi)
                #pragma unroll
                for (int ni = 0; ni < 4; ++ni) {
                    MMA16816(acc[mi][ni], ah[mi], bh[ni]);
                    MMA16816(acc[mi][ni], al[mi], bh[ni]);
                    MMA16816(acc[mi][ni], ah[mi], bl[ni]);
                }
        }
        __syncthreads();
    }

    __nv_bfloat16* Ch = (sel == 0) ? g_Qh : g_Kh;
    __nv_bfloat16* Cl = (sel == 0) ? g_Ql : g_Kl;
    const int mbase = (int)row0 + wm * 64;
    const int nbase = col0l + wn * 32;
    #pragma unroll
    for (int mi = 0; mi < 4; ++mi) {
        #pragma unroll
        for (int ni = 0; ni < 4; ++ni) {
            int r = mbase + mi * 16 + (lane >> 2);
            int c = nbase + ni * 8 + (lane & 3) * 2;      // 0..767 local
            float b0 = bias[c], b1 = bias[c + 1];
            float v00 = acc[mi][ni][0] + b0, v01 = acc[mi][ni][1] + b1;
            float v10 = acc[mi][ni][2] + b0, v11 = acc[mi][ni][3] + b1;
            if (sel < 2) {
                __nv_bfloat162 lo0, lo1;
                __nv_bfloat162 hi0 = split_hi2(v00, v01, lo0);
                __nv_bfloat162 hi1 = split_hi2(v10, v11, lo1);
                *(__nv_bfloat162*)&Ch[(size_t)r * DIM + c] = hi0;
                *(__nv_bfloat162*)&Cl[(size_t)r * DIM + c] = lo0;
                *(__nv_bfloat162*)&Ch[(size_t)(r + 8) * DIM + c] = hi1;
                *(__nv_bfloat162*)&Cl[(size_t)(r + 8) * DIM + c] = lo1;
            } else {
                int b = r >> 10, n = r & 1023;
                size_t row_c0 = ((size_t)b * NHEAD + (c >> 6)) * HDIM + (c & 63);
                size_t row_c1 = ((size_t)b * NHEAD + ((c + 1) >> 6)) * HDIM + ((c + 1) & 63);
                __nv_bfloat16 h, l;
                h = __float2bfloat16(v00); l = __float2bfloat16(v00 - __bfloat162float(h));
                g_VTh[row_c0 * SEQ + n] = h; g_VTl[row_c0 * SEQ + n] = l;
                h = __float2bfloat16(v01); l = __float2bfloat16(v01 - __bfloat162float(h));
                g_VTh[row_c1 * SEQ + n] = h; g_VTl[row_c1 * SEQ + n] = l;
                h = __float2bfloat16(v10); l = __float2bfloat16(v10 - __bfloat162float(h));
                g_VTh[row_c0 * SEQ + n + 8] = h; g_VTl[row_c0 * SEQ + n + 8] = l;
                h = __float2bfloat16(v11); l = __float2bfloat16(v11 - __bfloat162float(h));
                g_VTh[row_c1 * SEQ + n + 8] = h; g_VTl[row_c1 * SEQ + n + 8] = l;
            }
        }
    }
}

// ---------------------------------------------------------------------------
// out_proj GEMM: out = O @ Wo^T + bo (fp32 out), 3-stage.
// ---------------------------------------------------------------------------
__global__ __launch_bounds__(256, 1)
void gemm_oproj(const __nv_bfloat16* __restrict__ Ah,
                const __nv_bfloat16* __restrict__ Al,
                const __nv_bfloat16* __restrict__ Bh,
                const __nv_bfloat16* __restrict__ Bl,
                const float* __restrict__ bias, float* __restrict__ Cf) {
    extern __shared__ char sm[];
    const int tid = threadIdx.x;
    const int lane = tid & 31;
    const int warp = tid >> 5;
    const int wm = warp >> 2, wn = warp & 3;
    const size_t row0 = (size_t)blockIdx.y * 128;
    const size_t col0 = (size_t)blockIdx.x * 128;
    const uint32_t smb = smem_u32(sm);

    float acc[4][4][4];
    #pragma unroll
    for (int i = 0; i < 4; ++i)
        #pragma unroll
        for (int j = 0; j < 4; ++j)
            #pragma unroll
            for (int q = 0; q < 4; ++q) acc[i][j][q] = 0.f;

    const int r_c0 = tid >> 2, j_c0 = tid & 3;
    const int r_c1 = (tid + 256) >> 2, j_c1 = (tid + 256) & 3;

    auto issue = [&](int s, int st) {
        const int k0 = s * 32;
        const uint32_t sb = smb + st * STAGE_B;
        uint32_t d0 = sb + r_c0 * 80 + j_c0 * 16;
        CP_ASYNC16(d0,            Ah + (row0 + r_c0) * DIM + k0 + j_c0 * 8);
        CP_ASYNC16(d0 + TILE_B,   Al + (row0 + r_c0) * DIM + k0 + j_c0 * 8);
        CP_ASYNC16(d0 + 2*TILE_B, Bh + (col0 + r_c0) * DIM + k0 + j_c0 * 8);
        CP_ASYNC16(d0 + 3*TILE_B, Bl + (col0 + r_c0) * DIM + k0 + j_c0 * 8);
        uint32_t d1 = sb + r_c1 * 80 + j_c1 * 16;
        CP_ASYNC16(d1,            Ah + (row0 + r_c1) * DIM + k0 + j_c1 * 8);
        CP_ASYNC16(d1 + TILE_B,   Al + (row0 + r_c1) * DIM + k0 + j_c1 * 8);
        CP_ASYNC16(d1 + 2*TILE_B, Bh + (col0 + r_c1) * DIM + k0 + j_c1 * 8);
        CP_ASYNC16(d1 + 3*TILE_B, Bl + (col0 + r_c1) * DIM + k0 + j_c1 * 8);
        CP_COMMIT();
    };

    const int a_row_l = (lane & 15);
    const int a_col_l = (lane >> 4) << 3;
    const int b_row_l = (lane & 7) + ((lane >> 4) << 3);
    const int b_col_l = ((lane >> 3) & 1) << 3;

    issue(0, 0); issue(1, 1);
    for (int s = 0; s < 24; ++s) {
        if (s + 2 < 24) { issue(s + 2, (s + 2) % 3); CP_WAIT2(); }
        else if (s + 1 < 24) CP_WAIT1();
        else CP_WAIT0();
        __syncthreads();
        const uint32_t sb = smb + (s % 3) * STAGE_B;
        const uint32_t tAh = sb, tAl = sb + TILE_B;
        const uint32_t tBh = sb + 2 * TILE_B, tBl = sb + 3 * TILE_B;
        #pragma unroll
        for (int ks = 0; ks < 2; ++ks) {
            uint32_t ah[4][4], al[4][4], bh[4][2], bl[4][2];
            #pragma unroll
            for (int mi = 0; mi < 4; ++mi) {
                uint32_t off = (uint32_t)((wm * 64 + mi * 16 + a_row_l) * 80 +
                                          (ks * 16 + a_col_l) * 2);
                LDSM_X4(ah[mi][0], ah[mi][1], ah[mi][2], ah[mi][3], tAh + off);
                LDSM_X4(al[mi][0], al[mi][1], al[mi][2], al[mi][3], tAl + off);
            }
            #pragma unroll
            for (int nj = 0; nj < 2; ++nj) {
                uint32_t off = (uint32_t)((wn * 32 + nj * 16 + b_row_l) * 80 +
                                          (ks * 16 + b_col_l) * 2);
                uint32_t t0, t1, t2, t3;
                LDSM_X4(t0, t1, t2, t3, tBh + off);
                bh[nj * 2][0] = t0; bh[nj * 2][1] = t1;
                bh[nj * 2 + 1][0] = t2; bh[nj * 2 + 1][1] = t3;
                LDSM_X4(t0, t1, t2, t3, tBl + off);
                bl[nj * 2][0] = t0; bl[nj * 2][1] = t1;
                bl[nj * 2 + 1][0] = t2; bl[nj * 2 + 1][1] = t3;
            }
            #pragma unroll
            for (int mi = 0; mi < 4; ++mi)
                #pragma unroll
                for (int ni = 0; ni < 4; ++ni) {
                    MMA16816(acc[mi][ni], ah[mi], bh[ni]);
                    MMA16816(acc[mi][ni], al[mi], bh[ni]);
                    MMA16816(acc[mi][ni], ah[mi], bl[ni]);
                }
        }
        __syncthreads();
    }

    const int mbase = (int)row0 + wm * 64;
    const int nbase = (int)col0 + wn * 32;
    #pragma unroll
    for (int mi = 0; mi < 4; ++mi) {
        #pragma unroll
        for (int ni = 0; ni < 4; ++ni) {
            int r = mbase + mi * 16 + (lane >> 2);
            int c = nbase + ni * 8 + (lane & 3) * 2;
            float b0 = bias[c], b1 = bias[c + 1];
            *(float2*)&Cf[(size_t)r * DIM + c] =
                make_float2(acc[mi][ni][0] + b0, acc[mi][ni][1] + b1);
            *(float2*)&Cf[(size_t)(r + 8) * DIM + c] =
                make_float2(acc[mi][ni][2] + b0, acc[mi][ni][3] + b1);
        }
    }
}

// ---------------------------------------------------------------------------
// Fused scores + softmax (unchanged from R5).
// ---------------------------------------------------------------------------
#define KST 72
#define AF_QSZ (32 * KST * 2)
#define AF_KSZ (128 * KST * 2)
#define AF_Q0  0
#define AF_Q1  AF_QSZ
#define AF_K0  (2 * AF_QSZ)
#define AF_RED (AF_K0 + 4 * AF_KSZ)
#define AF_SMEM (AF_RED + 1024)

__global__ __launch_bounds__(256, 1)
void attn_fused(float* __restrict__ Wt) {
    extern __shared__ char sm[];
    const uint32_t smb = smem_u32(sm);
    float* red_max = (float*)(sm + AF_RED);
    float* red_sum = (float*)(sm + AF_RED + 512);
    const int tid = threadIdx.x;
    const int lane = tid & 31;
    const int warp = tid >> 5;
    const int wm = warp >> 2, wn = warp & 3;
    const int bh = blockIdx.y;
    const int b = bh / NHEAD, h = bh - b * NHEAD;
    const size_t i0 = (size_t)blockIdx.x * 32;
    const __nv_bfloat16* Qh = g_Qh + ((size_t)b * SEQ) * DIM + h * HDIM;
    const __nv_bfloat16* Ql = g_Ql + ((size_t)b * SEQ) * DIM + h * HDIM;
    const __nv_bfloat16* Kh = g_Kh + ((size_t)b * SEQ) * DIM + h * HDIM;
    const __nv_bfloat16* Kl = g_Kl + ((size_t)b * SEQ) * DIM + h * HDIM;

    float acc[8][4][4];
    #pragma unroll
    for (int c = 0; c < 8; ++c)
        #pragma unroll
        for (int j = 0; j < 4; ++j)
            #pragma unroll
            for (int q = 0; q < 4; ++q) acc[c][j][q] = 0.f;

    {
        int r = tid >> 3, j = tid & 7;
        uint32_t d = smb + AF_Q0 + r * 144 + j * 16;
        CP_ASYNC16(d,          Qh + (i0 + r) * DIM + j * 8);
        CP_ASYNC16(d + AF_QSZ, Ql + (i0 + r) * DIM + j * 8);
        #pragma unroll
        for (int p = 0; p < 4; ++p) {
            int idx = tid + p * 256;
            int kr = idx >> 3, kj = idx & 7;
            uint32_t kd = smb + AF_K0 + kr * 144 + kj * 16;
            CP_ASYNC16(kd,          Kh + (size_t)kr * DIM + kj * 8);
            CP_ASYNC16(kd + AF_KSZ, Kl + (size_t)kr * DIM + kj * 8);
        }
        CP_COMMIT();
        #pragma unroll
        for (int p = 0; p < 4; ++p) {
            int idx = tid + p * 256;
            int kr = idx >> 3, kj = idx & 7;
            uint32_t kd = smb + AF_K0 + 2 * AF_KSZ + kr * 144 + kj * 16;
            CP_ASYNC16(kd,          Kh + (size_t)(128 + kr) * DIM + kj * 8);
            CP_ASYNC16(kd + AF_KSZ, Kl + (size_t)(128 + kr) * DIM + kj * 8);
        }
        CP_COMMIT();
    }

    const int a_row_l = (lane & 15);
    const int a_col_l = (lane >> 4) << 3;
    const int b_row_l = (lane & 7) + ((lane >> 4) << 3);
    const int b_col_l = ((lane >> 3) & 1) << 3;

    uint32_t qh[4][4], ql[4][4];
    bool qloaded = false;

    for (int c = 0; c < 8; ++c) {
        if (c < 7) CP_WAIT1(); else CP_WAIT0();
        __syncthreads();
        if (!qloaded) {
            #pragma unroll
            for (int ks = 0; ks < 4; ++ks) {
                uint32_t off = (uint32_t)((wm * 16 + a_row_l) * 144 +
                                          (ks * 16 + a_col_l) * 2);
                LDSM_X4(qh[ks][0], qh[ks][1], qh[ks][2], qh[ks][3],
                        smb + AF_Q0 + off);
                LDSM_X4(ql[ks][0], ql[ks][1], ql[ks][2], ql[ks][3],
                        smb + AF_Q1 + off);
            }
            qloaded = true;
        }
        const uint32_t kb = smb + AF_K0 + (c & 1) * 2 * AF_KSZ;
        #pragma unroll
        for (int ks = 0; ks < 4; ++ks) {
            uint32_t bh2[4][2], bl2[4][2];
            #pragma unroll
            for (int nj = 0; nj < 2; ++nj) {
                uint32_t off = (uint32_t)((wn * 32 + nj * 16 + b_row_l) * 144 +
                                          (ks * 16 + b_col_l) * 2);
                uint32_t t0, t1, t2, t3;
                LDSM_X4(t0, t1, t2, t3, kb + off);
                bh2[nj * 2][0] = t0; bh2[nj * 2][1] = t1;
                bh2[nj * 2 + 1][0] = t2; bh2[nj * 2 + 1][1] = t3;
                LDSM_X4(t0, t1, t2, t3, kb + AF_KSZ + off);
                bl2[nj * 2][0] = t0; bl2[nj * 2][1] = t1;
                bl2[nj * 2 + 1][0] = t2; bl2[nj * 2 + 1][1] = t3;
            }
            #pragma unroll
            for (int ni = 0; ni < 4; ++ni) {
                MMA16816(acc[c][ni], qh[ks], bh2[ni]);
                MMA16816(acc[c][ni], ql[ks], bh2[ni]);
                MMA16816(acc[c][ni], qh[ks], bl2[ni]);
            }
        }
        __syncthreads();
        if (c + 2 < 8) {
            const uint32_t kd0 = smb + AF_K0 + (c & 1) * 2 * AF_KSZ;
            const size_t j0n = (size_t)(c + 2) * 128;
            #pragma unroll
            for (int p = 0; p < 4; ++p) {
                int idx = tid + p * 256;
                int kr = idx >> 3, kj = idx & 7;
                uint32_t kd = kd0 + kr * 144 + kj * 16;
                CP_ASYNC16(kd,          Kh + (j0n + kr) * DIM + kj * 8);
                CP_ASYNC16(kd + AF_KSZ, Kl + (j0n + kr) * DIM + kj * 8);
            }
            CP_COMMIT();
        }
    }

    #pragma unroll
    for (int c = 0; c < 8; ++c)
        #pragma unroll
        for (int j = 0; j < 4; ++j)
            #pragma unroll
            for (int q = 0; q < 4; ++q) acc[c][j][q] *= 0.125f;

    const int R0 = wm * 16 + (lane >> 2);
    const int R1 = R0 + 8;

    float m0 = -1e30f, m1 = -1e30f;
    #pragma unroll
    for (int c = 0; c < 8; ++c)
        #pragma unroll
        for (int j = 0; j < 4; ++j) {
            m0 = fmaxf(m0, fmaxf(acc[c][j][0], acc[c][j][1]));
            m1 = fmaxf(m1, fmaxf(acc[c][j][2], acc[c][j][3]));
        }
    m0 = fmaxf(m0, __shfl_xor_sync(~0u, m0, 1));
    m0 = fmaxf(m0, __shfl_xor_sync(~0u, m0, 2));
    m1 = fmaxf(m1, __shfl_xor_sync(~0u, m1, 1));
    m1 = fmaxf(m1, __shfl_xor_sync(~0u, m1, 2));
    if ((lane & 3) == 0) {
        red_max[R0 * 4 + wn] = m0;
        red_max[R1 * 4 + wn] = m1;
    }
    __syncthreads();
    m0 = fmaxf(fmaxf(red_max[R0 * 4 + 0], red_max[R0 * 4 + 1]),
               fmaxf(red_max[R0 * 4 + 2], red_max[R0 * 4 + 3]));
    m1 = fmaxf(fmaxf(red_max[R1 * 4 + 0], red_max[R1 * 4 + 1]),
               fmaxf(red_max[R1 * 4 + 2], red_max[R1 * 4 + 3]));

    float s0 = 0.f, s1 = 0.f;
    #pragma unroll
    for (int c = 0; c < 8; ++c)
        #pragma unroll
        for (int j = 0; j < 4; ++j) {
            acc[c][j][0] = __expf(acc[c][j][0] - m0);
            acc[c][j][1] = __expf(acc[c][j][1] - m0);
            acc[c][j][2] = __expf(acc[c][j][2] - m1);
            acc[c][j][3] = __expf(acc[c][j][3] - m1);
            s0 += acc[c][j][0] + acc[c][j][1];
            s1 += acc[c][j][2] + acc[c][j][3];
        }
    s0 += __shfl_xor_sync(~0u, s0, 1);
    s0 += __shfl_xor_sync(~0u, s0, 2);
    s1 += __shfl_xor_sync(~0u, s1, 1);
    s1 += __shfl_xor_sync(~0u, s1, 2);
    if ((lane & 3) == 0) {
        red_sum[R0 * 4 + wn] = s0;
        red_sum[R1 * 4 + wn] = s1;
    }
    __syncthreads();
    s0 = red_sum[R0 * 4 + 0] + red_sum[R0 * 4 + 1] +
         red_sum[R0 * 4 + 2] + red_sum[R0 * 4 + 3];
    s1 = red_sum[R1 * 4 + 0] + red_sum[R1 * 4 + 1] +
         red_sum[R1 * 4 + 2] + red_sum[R1 * 4 + 3];
    float inv0 = 1.0f / s0, inv1 = 1.0f / s1;

    float* Wb = Wt + ((size_t)bh * SEQ + i0) * SEQ;
    #pragma unroll
    for (int c = 0; c < 8; ++c)
        #pragma unroll
        for (int j = 0; j < 4; ++j) {
            int col = c * 128 + wn * 32 + j * 8 + (lane & 3) * 2;
            *(float2*)&Wb[(size_t)R0 * SEQ + col] =
                make_float2(acc[c][j][0] * inv0, acc[c][j][1] * inv0);
            *(float2*)&Wb[(size_t)R1 * SEQ + col] =
                make_float2(acc[c][j][2] * inv1, acc[c][j][3] * inv1);
        }
}

// ---------------------------------------------------------------------------
// O = P @ V (fp32 P from weights; in-kernel bf16 split; VT via cp.async).
// ---------------------------------------------------------------------------
#define AV_ATILE 20480
#define AV_BTILE 5120
#define AV_ASTG  (2 * AV_ATILE)
#define AV_BSTG  (2 * AV_BTILE)
#define AV_B0    (2 * AV_ASTG)
#define AV_SMEM  (2 * AV_ASTG + 2 * AV_BSTG)

__global__ __launch_bounds__(256, 1)
void av_mma(const float* __restrict__ Wt) {
    extern __shared__ char sm[];
    const int tid = threadIdx.x;
    const int lane = tid & 31;
    const int warp = tid >> 5;
    const int wm = warp >> 1, wn = warp & 1;
    const int bh = blockIdx.z;
    const int b = bh / NHEAD, h = bh - b * NHEAD;
    const size_t m0 = (size_t)blockIdx.y * 256;
    const uint32_t smb = smem_u32(sm);
    const float* P = Wt + ((size_t)bh * SEQ + m0) * SEQ;
    const __nv_bfloat16* Bh = g_VTh + (size_t)bh * HDIM * SEQ;
    const __nv_bfloat16* Bl = g_VTl + (size_t)bh * HDIM * SEQ;

    float acc[4][4][4];
    #pragma unroll
    for (int i = 0; i < 4; ++i)
        #pragma unroll
        for (int j = 0; j < 4; ++j)
            #pragma unroll
            for (int q = 0; q < 4; ++q) acc[i][j][q] = 0.f;

    const int ar = tid >> 3, aj = tid & 7;

    auto issueB = [&](int s, int st) {
        const int k0 = s * 32;
        int r = tid >> 2, j = tid & 3;
        uint32_t d = smb + AV_B0 + st * AV_BSTG + r * 80 + j * 16;
        CP_ASYNC16(d,            Bh + (size_t)r * SEQ + k0 + j * 8);
        CP_ASYNC16(d + AV_BTILE, Bl + (size_t)r * SEQ + k0 + j * 8);
        CP_COMMIT();
    };

    float4 areg[8];
    auto ldgA = [&](int s) {
        const int k0 = s * 32;
        #pragma unroll
        for (int g = 0; g < 8; ++g)
            areg[g] = *(const float4*)&P[(size_t)(ar + 32 * g) * SEQ + k0 + aj * 4];
    };

    const int a_row_l = (lane & 15);
    const int a_col_l = (lane >> 4) << 3;
    const int b_row_l = (lane & 7) + ((lane >> 4) << 3);
    const int b_col_l = ((lane >> 3) & 1) << 3;

    issueB(0, 0);
    issueB(1, 1);
    ldgA(0);
    for (int s = 0; s < 32; ++s) {
        {
            const uint32_t ab = smb + (s & 1) * AV_ASTG;
            #pragma unroll
            for (int g = 0; g < 8; ++g) {
                float4 v = areg[g];
                __nv_bfloat162 lo0, lo1;
                __nv_bfloat162 hi0 = split_hi2(v.x, v.y, lo0);
                __nv_bfloat162 hi1 = split_hi2(v.z, v.w, lo1);
                uint32_t d = ab + (ar + 32 * g) * 80 + aj * 8;
                *(__nv_bfloat162*)(sm + (d - smb)) = hi0;
                *(__nv_bfloat162*)(sm + (d - smb) + 4) = hi1;
                *(__nv_bfloat162*)(sm + (d - smb) + AV_ATILE) = lo0;
                *(__nv_bfloat162*)(sm + (d - smb) + AV_ATILE + 4) = lo1;
            }
        }
        if (s < 31) CP_WAIT1(); else CP_WAIT0();
        __syncthreads();
        if (s + 1 < 32) ldgA(s + 1);

        const uint32_t ab = smb + (s & 1) * AV_ASTG;
        const uint32_t tAh = ab, tAl = ab + AV_ATILE;
        const uint32_t bb = smb + AV_B0 + (s & 1) * AV_BSTG;
        const uint32_t tBh = bb, tBl = bb + AV_BTILE;
        #pragma unroll
        for (int ks = 0; ks < 2; ++ks) {
            uint32_t ah[4][4], al[4][4], bh2[4][2], bl2[4][2];
            #pragma unroll
            for (int mi = 0; mi < 4; ++mi) {
                uint32_t off = (uint32_t)((wm * 64 + mi * 16 + a_row_l) * 80 +
                                          (ks * 16 + a_col_l) * 2);
                LDSM_X4(ah[mi][0], ah[mi][1], ah[mi][2], ah[mi][3], tAh + off);
                LDSM_X4(al[mi][0], al[mi][1], al[mi][2], al[mi][3], tAl + off);
            }
            #pragma unroll
            for (int nj = 0; nj < 2; ++nj) {
                uint32_t off = (uint32_t)((wn * 32 + nj * 16 + b_row_l) * 80 +
                                          (ks * 16 + b_col_l) * 2);
                uint32_t t0, t1, t2, t3;
                LDSM_X4(t0, t1, t2, t3, tBh + off);
                bh2[nj * 2][0] = t0; bh2[nj * 2][1] = t1;
                bh2[nj * 2 + 1][0] = t2; bh2[nj * 2 + 1][1] = t3;
                LDSM_X4(t0, t1, t2, t3, tBl + off);
                bl2[nj * 2][0] = t0; bl2[nj * 2][1] = t1;
                bl2[nj * 2 + 1][0] = t2; bl2[nj * 2 + 1][1] = t3;
            }
            #pragma unroll
            for (int mi = 0; mi < 4; ++mi)
                #pragma unroll
                for (int ni = 0; ni < 4; ++ni) {
                    MMA16816(acc[mi][ni], ah[mi], bh2[ni]);
                    MMA16816(acc[mi][ni], al[mi], bh2[ni]);
                    MMA16816(acc[mi][ni], ah[mi], bl2[ni]);
                }
        }
        __syncthreads();
        if (s + 2 < 32) issueB(s + 2, (s) & 1);
    }

    #pragma unroll
    for (int mi = 0; mi < 4; ++mi) {
        #pragma unroll
        for (int ni = 0; ni < 4; ++ni) {
            int rl = wm * 64 + mi * 16 + (lane >> 2);
            int cl = wn * 32 + ni * 8 + (lane & 3) * 2;
            size_t r = (size_t)b * SEQ + m0 + rl;
            size_t c = h * HDIM + cl;
            __nv_bfloat162 lo0, lo1;
            __nv_bfloat162 hi0 = split_hi2(acc[mi][ni][0], acc[mi][ni][1], lo0);
            __nv_bfloat162 hi1 = split_hi2(acc[mi][ni][2], acc[mi][ni][3], lo1);
            *(__nv_bfloat162*)&g_Oh[r * DIM + c] = hi0;
            *(__nv_bfloat162*)&g_Ol[r * DIM + c] = lo0;
            *(__nv_bfloat162*)&g_Oh[(r + 8) * DIM + c] = hi1;
            *(__nv_bfloat162*)&g_Ol[(r + 8) * DIM + c] = lo1;
        }
    }
}

// ---------------------------------------------------------------------------
extern "C" void kernel_launch(void* const* d_in, const int* in_sizes, int n_in,
                              void* d_out, int out_size) {
    const float* x  = (const float*)d_in[0];
    const float* Wq = (const float*)d_in[1];
    const float* bq = (const float*)d_in[2];
    const float* Wk = (const float*)d_in[3];
    const float* bk = (const float*)d_in[4];
    const float* Wv = (const float*)d_in[5];
    const float* bv = (const float*)d_in[6];
    const float* Wo = (const float*)d_in[7];
    const float* bo = (const float*)d_in[8];

    float* out = (float*)d_out;
    float* wts = out + OUT_OFF;

    cudaFuncSetAttribute(gemm_qkv,
                         cudaFuncAttributeMaxDynamicSharedMemorySize, GSMEM3);
    cudaFuncSetAttribute(gemm_oproj,
                         cudaFuncAttributeMaxDynamicSharedMemorySize, GSMEM3);
    cudaFuncSetAttribute(attn_fused,
                         cudaFuncAttributeMaxDynamicSharedMemorySize, AF_SMEM);
    cudaFuncSetAttribute(av_mma,
                         cudaFuncAttributeMaxDynamicSharedMemorySize, AV_SMEM);

    __nv_bfloat16 *Xh, *Xl, *Oh, *Ol, *WTh, *WTl;
    cudaGetSymbolAddress((void**)&Xh, g_Xh);
    cudaGetSymbolAddress((void**)&Xl, g_Xl);
    cudaGetSymbolAddress((void**)&Oh, g_Oh);
    cudaGetSymbolAddress((void**)&Ol, g_Ol);
    cudaGetSymbolAddress((void**)&WTh, g_WTh);
    cudaGetSymbolAddress((void**)&WTl, g_WTl);

    const int NELEM = MROWS * DIM;
    split_kernel<<<NELEM / 4 / 256, 256>>>(x, Xh, Xl, NELEM / 4);
    splitT4<<<dim3(DIM / 32, DIM / 32, 4), dim3(32, 8)>>>(Wq, Wk, Wv, Wo,
                                                          WTh, WTl);

    gemm_qkv<<<dim3(18, MROWS / 128), 256, GSMEM3>>>(bq, bk, bv);

    attn_fused<<<dim3(SEQ / 32, BH), 256, AF_SMEM>>>(wts);
    av_mma<<<dim3(1, SEQ / 256, BH), 256, AV_SMEM>>>(wts);

    gemm_oproj<<<dim3(DIM / 128, MROWS / 128), 256, GSMEM3>>>(
        Oh, Ol, WTh + 3 * DIM * DIM, WTl + 3 * DIM * DIM, bo, out);
}